// round 12
// baseline (speedup 1.0000x reference)
#include <cuda_runtime.h>
#include <cuda_bf16.h>
#include <math.h>
#include <stdint.h>

#define S_LEN 3072
#define DIM   2048
#define NH    16
#define HD    128
#define K3    (3*DIM)   // 6144: [hi | hi | lo] x [hi | lo | hi]

// ---------------- scratch (device globals; no allocations allowed) ----------
__device__ __align__(16) float g_qkv[S_LEN * 3 * DIM];           // [s][q|k|v]
__device__ __align__(16) float g_bias3[3 * DIM];
__device__ __align__(16) __nv_bfloat16 g_x3 [S_LEN * K3];
__device__ __align__(16) __nv_bfloat16 g_ao3[S_LEN * K3];
__device__ __align__(16) __nv_bfloat16 g_w3 [4][DIM * K3];
__device__ __align__(16) __nv_bfloat16 g_qs [NH * S_LEN * 256]; // [h][s][hi128|lo128]
__device__ __align__(16) __nv_bfloat16 g_ks [NH * S_LEN * 256];
__device__ __align__(16) __nv_bfloat16 g_vt [NH * 256 * S_LEN]; // [h][d:hi,d+128:lo][s]

// ---------------- PTX helpers ----------------------------------------------
__device__ __forceinline__ uint32_t smem_u32(const void* p) {
    uint32_t a;
    asm("{ .reg .u64 t; cvta.to.shared.u64 t, %1; cvt.u32.u64 %0, t; }" : "=r"(a) : "l"(p));
    return a;
}
__device__ __forceinline__ void cp_async16(uint32_t saddr, const void* g) {
    asm volatile("cp.async.cg.shared.global [%0], [%1], 16;" :: "r"(saddr), "l"(g));
}
#define CP_COMMIT() asm volatile("cp.async.commit_group;" ::: "memory")
#define CP_WAIT2()  asm volatile("cp.async.wait_group 2;" ::: "memory")
#define CP_WAIT1()  asm volatile("cp.async.wait_group 1;" ::: "memory")
#define CP_WAIT0()  asm volatile("cp.async.wait_group 0;" ::: "memory")

__device__ __forceinline__ void ldmx4(uint32_t& r0, uint32_t& r1, uint32_t& r2, uint32_t& r3,
                                      uint32_t addr) {
    asm volatile("ldmatrix.sync.aligned.m8n8.x4.shared.b16 {%0,%1,%2,%3}, [%4];"
                 : "=r"(r0), "=r"(r1), "=r"(r2), "=r"(r3) : "r"(addr));
}
__device__ __forceinline__ void mma_bf16(float* c, const uint32_t* a, uint32_t b0, uint32_t b1) {
    asm volatile("mma.sync.aligned.m16n8k16.row.col.f32.bf16.bf16.f32 "
                 "{%0,%1,%2,%3}, {%4,%5,%6,%7}, {%8,%9}, {%0,%1,%2,%3};"
                 : "+f"(c[0]), "+f"(c[1]), "+f"(c[2]), "+f"(c[3])
                 : "r"(a[0]), "r"(a[1]), "r"(a[2]), "r"(a[3]), "r"(b0), "r"(b1));
}
__device__ __forceinline__ void split2(float a, float b, uint32_t& hi, uint32_t& lo) {
    __nv_bfloat16 ha = __float2bfloat16(a), hb = __float2bfloat16(b);
    __nv_bfloat16 la = __float2bfloat16(a - __bfloat162float(ha));
    __nv_bfloat16 lb = __float2bfloat16(b - __bfloat162float(hb));
    __nv_bfloat162 H; H.x = ha; H.y = hb;
    __nv_bfloat162 L; L.x = la; L.y = lb;
    hi = *reinterpret_cast<uint32_t*>(&H);
    lo = *reinterpret_cast<uint32_t*>(&L);
}

// ---------------- fused split-bf16 conversion: x + 4 weights (float4) -------
#define NXQ (S_LEN * DIM / 4)
#define NWQ (DIM * DIM / 4)
#define CVT_BLOCKS ((NXQ + 4 * NWQ) / 256)

__global__ __launch_bounds__(256)
void cvt_all_kernel(const float* __restrict__ x,
                    const float* __restrict__ Wq, const float* __restrict__ Wk,
                    const float* __restrict__ Wv, const float* __restrict__ Wo,
                    __nv_bfloat16* __restrict__ x3, __nv_bfloat16* __restrict__ w3)
{
    int p = blockIdx.x * 256 + threadIdx.x;
    const float* src;
    __nv_bfloat16* dst;
    int mode, lp;
    if (p < NXQ) {
        src = x; dst = x3; mode = 0; lp = p;
    } else {
        int q = (p - NXQ) >> 20;
        lp = (p - NXQ) & (NWQ - 1);
        src = (q == 0) ? Wq : (q == 1) ? Wk : (q == 2) ? Wv : Wo;
        dst = w3 + (size_t)q * DIM * K3;
        mode = 1;
    }
    int i = lp * 4;
    float4 v = *(const float4*)&src[i];
    uint32_t hi0, lo0, hi1, lo1;
    split2(v.x, v.y, hi0, lo0);
    split2(v.z, v.w, hi1, lo1);
    uint2 hip = {hi0, hi1};
    uint2 lop = {lo0, lo1};
    int row = i >> 11;
    int c   = i & 2047;
    __nv_bfloat16* base = dst + (size_t)row * K3 + c;
    if (mode == 0) {
        *(uint2*)&base[0]       = hip;
        *(uint2*)&base[DIM]     = hip;
        *(uint2*)&base[2 * DIM] = lop;
    } else {
        *(uint2*)&base[0]       = hip;
        *(uint2*)&base[DIM]     = lop;
        *(uint2*)&base[2 * DIM] = hip;
    }
}

__global__ __launch_bounds__(256)
void bias3_kernel(const float* __restrict__ bq, const float* __restrict__ bk,
                  const float* __restrict__ bv, float* __restrict__ dst)
{
    int i = blockIdx.x * 256 + threadIdx.x;
    if (i >= 3 * DIM) return;
    dst[i] = (i < DIM) ? bq[i] : (i < 2 * DIM ? bk[i - DIM] : bv[i - 2 * DIM]);
}

// ---------------- mma.sync GEMM: CTA 128x128, 3-stage cp.async, 2 CTA/SM ----
#define GBM 128
#define GBN 128
#define GBK 64
#define GSTAGES 3
#define GNITER (K3 / GBK)
#define TILE_B 16384
#define SMEM_G (GSTAGES * TILE_B * 2)   // 98304

__device__ __forceinline__ void g_load_stage(uint32_t sA, uint32_t sB,
    const __nv_bfloat16* __restrict__ A, const __nv_bfloat16* __restrict__ B,
    int bm, int bn, int kc, int tid)
{
#pragma unroll
    for (int i = 0; i < 4; i++) {
        int c = tid + i * 256;
        int row = c >> 3, cc = c & 7;
        cp_async16(sA + row * 128 + ((cc ^ (row & 7)) << 4),
                   A + (size_t)(bm + row) * K3 + kc + cc * 8);
    }
#pragma unroll
    for (int i = 0; i < 4; i++) {
        int c = tid + i * 256;
        int row = c >> 3, cc = c & 7;
        cp_async16(sB + row * 128 + ((cc ^ (row & 7)) << 4),
                   B + (size_t)(bn + row) * K3 + kc + cc * 8);
    }
}

__global__ __launch_bounds__(256, 2)
void gemm_mma_kernel(const __nv_bfloat16* __restrict__ A,
                     const __nv_bfloat16* __restrict__ B,
                     const float* __restrict__ bias, float* __restrict__ C, int Nn)
{
    extern __shared__ __align__(1024) char smem[];
    const uint32_t sb = smem_u32(smem);
    const uint32_t sAb = sb;
    const uint32_t sBb = sb + GSTAGES * TILE_B;

    const int tid = threadIdx.x;
    const int wid = tid >> 5, lane = tid & 31;
    const int bm = blockIdx.y * GBM, bn = blockIdx.x * GBN;
    const int wm = (wid & 1) * 64;
    const int wn = (wid >> 1) * 32;

    const int a_row = lane & 15;
    const int a_kh  = (lane >> 4);
    const int b_row = (lane & 7) + ((lane >> 4) << 3);
    const int b_kh  = (lane >> 3) & 1;

    float acc[4][4][4];
#pragma unroll
    for (int mt = 0; mt < 4; mt++)
#pragma unroll
        for (int nt = 0; nt < 4; nt++)
#pragma unroll
            for (int r = 0; r < 4; r++) acc[mt][nt][r] = 0.f;

#pragma unroll
    for (int s = 0; s < GSTAGES - 1; s++) {
        g_load_stage(sAb + s * TILE_B, sBb + s * TILE_B, A, B, bm, bn, s * GBK, tid);
        CP_COMMIT();
    }

    uint32_t a_base[4], b_base[2]; int a_xm[4], b_xm[2];
#pragma unroll
    for (int mt = 0; mt < 4; mt++) {
        int row = wm + mt * 16 + a_row;
        a_base[mt] = row * 128;
        a_xm[mt] = row & 7;
    }
#pragma unroll
    for (int np = 0; np < 2; np++) {
        int row = wn + np * 16 + b_row;
        b_base[np] = row * 128;
        b_xm[np] = row & 7;
    }

    int cs = 0, ls = GSTAGES - 1;
    for (int it = 0; it < GNITER; it++) {
        CP_WAIT1();
        __syncthreads();
        const uint32_t sA = sAb + cs * TILE_B;
        const uint32_t sB = sBb + cs * TILE_B;

#pragma unroll
        for (int ks = 0; ks < 4; ks++) {
            uint32_t af[4][4];
#pragma unroll
            for (int mt = 0; mt < 4; mt++)
                ldmx4(af[mt][0], af[mt][1], af[mt][2], af[mt][3],
                      sA + a_base[mt] + (((ks * 2 + a_kh) ^ a_xm[mt]) << 4));
            uint32_t bfr[2][4];
#pragma unroll
            for (int np = 0; np < 2; np++)
                ldmx4(bfr[np][0], bfr[np][1], bfr[np][2], bfr[np][3],
                      sB + b_base[np] + (((ks * 2 + b_kh) ^ b_xm[np]) << 4));
#pragma unroll
            for (int mt = 0; mt < 4; mt++)
#pragma unroll
                for (int nt = 0; nt < 4; nt++)
                    mma_bf16(acc[mt][nt], af[mt],
                             bfr[nt >> 1][(nt & 1) * 2], bfr[nt >> 1][(nt & 1) * 2 + 1]);
        }

        const int li = it + GSTAGES - 1;
        if (li < GNITER)
            g_load_stage(sAb + ls * TILE_B, sBb + ls * TILE_B, A, B, bm, bn, li * GBK, tid);
        CP_COMMIT();
        cs = (cs + 1 == GSTAGES) ? 0 : cs + 1;
        ls = (ls + 1 == GSTAGES) ? 0 : ls + 1;
    }

    const int tq = lane >> 2, tr4 = lane & 3;
#pragma unroll
    for (int mt = 0; mt < 4; mt++) {
#pragma unroll
        for (int nt = 0; nt < 4; nt++) {
            const int row = bm + wm + mt * 16 + tq;
            const int col = bn + wn + nt * 8 + tr4 * 2;
            const float b0 = bias[col], b1 = bias[col + 1];
            float2 v0 = {acc[mt][nt][0] + b0, acc[mt][nt][1] + b1};
            float2 v1 = {acc[mt][nt][2] + b0, acc[mt][nt][3] + b1};
            *(float2*)&C[(size_t)row * Nn + col]       = v0;
            *(float2*)&C[(size_t)(row + 8) * Nn + col] = v1;
        }
    }
}

// ---------------- fused RMSNorm+RoPE+split for q AND k ----------------------
__global__ __launch_bounds__(256)
void rms2_rope_split_kernel(const float* __restrict__ qkv,
                            const float* __restrict__ wq, const float* __restrict__ wk,
                            const float* __restrict__ cosb, const float* __restrict__ sinb,
                            __nv_bfloat16* __restrict__ qs, __nv_bfloat16* __restrict__ ks,
                            float qscale)
{
    const int row = blockIdx.x;
    const float* pq = qkv + (size_t)row * (3 * DIM);
    const float* pk = pq + DIM;
    const int tid = threadIdx.x;

    float ssq = 0.f, ssk = 0.f;
    for (int i = tid; i < DIM; i += 256) {
        float a = pq[i]; ssq += a * a;
        float b = pk[i]; ssk += b * b;
    }
#pragma unroll
    for (int off = 16; off > 0; off >>= 1) {
        ssq += __shfl_xor_sync(0xffffffffu, ssq, off);
        ssk += __shfl_xor_sync(0xffffffffu, ssk, off);
    }
    __shared__ float redq[8], redk[8];
    __shared__ float scq_s, sck_s;
    if ((tid & 31) == 0) { redq[tid >> 5] = ssq; redk[tid >> 5] = ssk; }
    __syncthreads();
    if (tid == 0) {
        float tq = 0.f, tk = 0.f;
#pragma unroll
        for (int i = 0; i < 8; i++) { tq += redq[i]; tk += redk[i]; }
        scq_s = rsqrtf(tq / (float)DIM + 1e-6f);
        sck_s = rsqrtf(tk / (float)DIM + 1e-6f);
    }
    __syncthreads();
    const float scq = scq_s, sck = sck_s;

    const float* crow = cosb + (size_t)row * HD;
    const float* srow = sinb + (size_t)row * HD;
    for (int pi = tid; pi < DIM / 2; pi += 256) {
        int i0 = 2 * pi;
        int h = i0 >> 7;
        int d = i0 & (HD - 1);
        float c = crow[d], s = srow[d];
        {
            float2 xv = *(const float2*)&pq[i0];
            float e = xv.x * scq * wq[i0];
            float o = xv.y * scq * wq[i0 + 1];
            float rx = (e * c - o * s) * qscale;
            float ry = (o * c + e * s) * qscale;
            uint32_t hi, lo;
            split2(rx, ry, hi, lo);
            __nv_bfloat16* base = qs + (size_t)h * S_LEN * 256 + (size_t)row * 256;
            *(uint32_t*)&base[d]       = hi;
            *(uint32_t*)&base[128 + d] = lo;
        }
        {
            float2 xv = *(const float2*)&pk[i0];
            float e = xv.x * sck * wk[i0];
            float o = xv.y * sck * wk[i0 + 1];
            float rx = e * c - o * s;
            float ry = o * c + e * s;
            uint32_t hi, lo;
            split2(rx, ry, hi, lo);
            __nv_bfloat16* base = ks + (size_t)h * S_LEN * 256 + (size_t)row * 256;
            *(uint32_t*)&base[d]       = hi;
            *(uint32_t*)&base[128 + d] = lo;
        }
    }
}

// ---------------- V transpose + split -> [NH][256][S], 4B stores ------------
__global__ __launch_bounds__(256)
void vsplit_t_kernel(const float* __restrict__ qkv, __nv_bfloat16* __restrict__ vt)
{
    __shared__ float tile[32][33];
    const int s0 = blockIdx.x * 32;
    const int c0 = blockIdx.y * 32;
    const int tx = threadIdx.x & 31;
    const int ty = threadIdx.x >> 5;

#pragma unroll
    for (int i = 0; i < 4; i++) {
        int r = ty + i * 8;
        tile[r][tx] = qkv[(size_t)(s0 + r) * (3 * DIM) + 2 * DIM + c0 + tx];
    }
    __syncthreads();
    const int sx = (threadIdx.x & 15) * 2;
    const int dr0 = threadIdx.x >> 4;
#pragma unroll
    for (int i = 0; i < 2; i++) {
        int dr = dr0 + i * 16;
        int dg = c0 + dr;
        int h = dg >> 7, d = dg & 127;
        float v0 = tile[sx][dr];
        float v1 = tile[sx + 1][dr];
        uint32_t hi, lo;
        split2(v0, v1, hi, lo);
        size_t base = (size_t)h * 256 * S_LEN;
        *(uint32_t*)&vt[base + (size_t)d * S_LEN + s0 + sx]         = hi;
        *(uint32_t*)&vt[base + (size_t)(d + 128) * S_LEN + s0 + sx] = lo;
    }
}

// ---------------- tensor-core flash attention: 4 warps x 32 rows ------------
// Q resident 64KB; KV 2-stage 2x64KB = 192KB. Each B-fragment feeds 12 MMAs.
#define ATH 128
#define QSM_B (128 * 512)
#define KST_B (64 * 512)
#define VST_B (256 * 128)
#define KV_ST (KST_B + VST_B)
#define ATTN_SMEM (QSM_B + 2 * KV_ST)   // 196608

__device__ __forceinline__ void attn_load_kv(uint32_t kvb,
    const __nv_bfloat16* __restrict__ ksrc0, const __nv_bfloat16* __restrict__ vsrc0,
    int kt, int tid)
{
    const __nv_bfloat16* ksrc = ksrc0 + (size_t)kt * 64 * 256;
#pragma unroll
    for (int u = 0; u < 16; u++) {
        int c = tid + u * ATH;
        int r = c >> 5, ch = c & 31;
        cp_async16(kvb + r * 512 + ((ch ^ (r & 7)) << 4), ksrc + (size_t)r * 256 + ch * 8);
    }
    const __nv_bfloat16* vsrc = vsrc0 + kt * 64;
    const uint32_t vb = kvb + KST_B;
#pragma unroll
    for (int u = 0; u < 16; u++) {
        int c = tid + u * ATH;
        int r = c >> 3, ch = c & 7;
        cp_async16(vb + r * 128 + ((ch ^ (r & 7)) << 4), vsrc + (size_t)r * S_LEN + ch * 8);
    }
}

__global__ __launch_bounds__(ATH, 1)
void attn_mma_kernel(const __nv_bfloat16* __restrict__ qs,
                     const __nv_bfloat16* __restrict__ ks,
                     const __nv_bfloat16* __restrict__ vt,
                     __nv_bfloat16* __restrict__ ao3, const int* __restrict__ seq_lens)
{
    extern __shared__ __align__(1024) char smem[];
    const uint32_t sb = smem_u32(smem);
    const uint32_t qsm = sb;
    const uint32_t kvb0 = sb + QSM_B;
    const int tid = threadIdx.x, lane = tid & 31, wid = tid >> 5;   // wid 0..3
    const int qb = blockIdx.x, h = blockIdx.y;

    const int seqlen = seq_lens[0];
    const int ntiles = (seqlen + 63) >> 6;

    const __nv_bfloat16* qsrc  = qs + ((size_t)h * S_LEN + qb * 128) * 256;
    const __nv_bfloat16* ksrc0 = ks + (size_t)h * S_LEN * 256;
    const __nv_bfloat16* vsrc0 = vt + (size_t)h * 256 * S_LEN;

    // Q load (64KB, 128 threads)
#pragma unroll
    for (int u = 0; u < 32; u++) {
        int c = tid + u * ATH;
        int r = c >> 5, ch = c & 31;
        cp_async16(qsm + r * 512 + ((ch ^ (r & 7)) << 4), qsrc + (size_t)r * 256 + ch * 8);
    }
    CP_COMMIT();
    attn_load_kv(kvb0, ksrc0, vsrc0, 0, tid);
    CP_COMMIT();
    CP_WAIT1();            // Q ready (KV0 may be in flight)
    __syncthreads();

    // geometry: 2 row-groups of 16 per warp
    const int a_k16 = lane >> 4;
    uint32_t a_off[2]; int a_x[2];
#pragma unroll
    for (int mg = 0; mg < 2; mg++) {
        int row = wid * 32 + mg * 16 + (lane & 15);
        a_off[mg] = row * 512;
        a_x[mg] = row & 7;
    }
    const int b_row = (lane & 7) + ((lane >> 4) << 3);
    const int b_k16 = (lane >> 3) & 1;

    uint32_t kb_off[4]; int kb_x[4];
#pragma unroll
    for (int np = 0; np < 4; np++) {
        int row = np * 16 + b_row;
        kb_off[np] = row * 512; kb_x[np] = row & 7;
    }
    uint32_t vb_off[8]; int vb_x[8];
#pragma unroll
    for (int np = 0; np < 8; np++) {
        int row = np * 16 + b_row;
        vb_off[np] = row * 128; vb_x[np] = row & 7;
    }

    float o[2][16][4];
#pragma unroll
    for (int mg = 0; mg < 2; mg++)
#pragma unroll
        for (int nt = 0; nt < 16; nt++)
#pragma unroll
            for (int c = 0; c < 4; c++) o[mg][nt][c] = 0.f;
    float mAr[2] = {-1e30f, -1e30f}, mBr[2] = {-1e30f, -1e30f};
    float lAr[2] = {0.f, 0.f},       lBr[2] = {0.f, 0.f};

    for (int kt = 0; kt < ntiles; kt++) {
        if (kt + 1 < ntiles) {
            attn_load_kv(kvb0 + ((kt + 1) & 1) * KV_ST, ksrc0, vsrc0, kt + 1, tid);
            CP_COMMIT();
            CP_WAIT1();
        } else {
            CP_WAIT0();
        }
        __syncthreads();
        const uint32_t ksm = kvb0 + (kt & 1) * KV_ST;
        const uint32_t vsm = ksm + KST_B;

        // ---- QK^T: both row-groups share each K fragment ----
        float s[2][8][4];
#pragma unroll
        for (int mg = 0; mg < 2; mg++)
#pragma unroll
            for (int nt = 0; nt < 8; nt++)
#pragma unroll
                for (int c = 0; c < 4; c++) s[mg][nt][c] = 0.f;

#pragma unroll
        for (int kst = 0; kst < 8; kst++) {
            uint32_t ah[2][4], al[2][4];
#pragma unroll
            for (int mg = 0; mg < 2; mg++) {
                ldmx4(ah[mg][0], ah[mg][1], ah[mg][2], ah[mg][3],
                      qsm + a_off[mg] + (((kst * 2 + a_k16) ^ a_x[mg]) << 4));
                ldmx4(al[mg][0], al[mg][1], al[mg][2], al[mg][3],
                      qsm + a_off[mg] + (((16 + kst * 2 + a_k16) ^ a_x[mg]) << 4));
            }
#pragma unroll
            for (int np = 0; np < 4; np++) {
                uint32_t bh[4], bl[4];
                ldmx4(bh[0], bh[1], bh[2], bh[3],
                      ksm + kb_off[np] + (((kst * 2 + b_k16) ^ kb_x[np]) << 4));
                ldmx4(bl[0], bl[1], bl[2], bl[3],
                      ksm + kb_off[np] + (((16 + kst * 2 + b_k16) ^ kb_x[np]) << 4));
#pragma unroll
                for (int mg = 0; mg < 2; mg++) {
                    mma_bf16(s[mg][2*np],   ah[mg], bh[0], bh[1]);
                    mma_bf16(s[mg][2*np+1], ah[mg], bh[2], bh[3]);
                    mma_bf16(s[mg][2*np],   ah[mg], bl[0], bl[1]);
                    mma_bf16(s[mg][2*np+1], ah[mg], bl[2], bl[3]);
                    mma_bf16(s[mg][2*np],   al[mg], bh[0], bh[1]);
                    mma_bf16(s[mg][2*np+1], al[mg], bh[2], bh[3]);
                }
            }
        }

        // ---- mask partial tile ----
        if (kt * 64 + 64 > seqlen) {
            const int kbase = kt * 64 + (lane & 3) * 2;
#pragma unroll
            for (int mg = 0; mg < 2; mg++)
#pragma unroll
                for (int nt = 0; nt < 8; nt++)
#pragma unroll
                    for (int c = 0; c < 4; c++) {
                        int gk = kbase + nt * 8 + (c & 1);
                        if (gk >= seqlen) s[mg][nt][c] = -1e30f;
                    }
        }

        // ---- rowmax per group ----
        float mnA[2], mnB[2], fAv[2], fBv[2];
#pragma unroll
        for (int mg = 0; mg < 2; mg++) {
            float pmA = -1e30f, pmB = -1e30f;
#pragma unroll
            for (int nt = 0; nt < 8; nt++) {
                pmA = fmaxf(pmA, fmaxf(s[mg][nt][0], s[mg][nt][1]));
                pmB = fmaxf(pmB, fmaxf(s[mg][nt][2], s[mg][nt][3]));
            }
            pmA = fmaxf(pmA, __shfl_xor_sync(0xffffffffu, pmA, 1));
            pmA = fmaxf(pmA, __shfl_xor_sync(0xffffffffu, pmA, 2));
            pmB = fmaxf(pmB, __shfl_xor_sync(0xffffffffu, pmB, 1));
            pmB = fmaxf(pmB, __shfl_xor_sync(0xffffffffu, pmB, 2));
            mnA[mg] = fmaxf(mAr[mg], pmA);
            mnB[mg] = fmaxf(mBr[mg], pmB);
            fAv[mg] = __expf(mAr[mg] - mnA[mg]);
            fBv[mg] = __expf(mBr[mg] - mnB[mg]);
        }
        float sumA[2] = {0.f, 0.f}, sumB[2] = {0.f, 0.f};

        // ---- chunked: exp + split + (kk==0: o-scale) + PV MMAs ----
#pragma unroll
        for (int kk = 0; kk < 4; kk++) {
            uint32_t ph[2][4], pl[2][4];
#pragma unroll
            for (int mg = 0; mg < 2; mg++) {
                const int n0 = 2 * kk, n1 = 2 * kk + 1;
                s[mg][n0][0] = __expf(s[mg][n0][0] - mnA[mg]); sumA[mg] += s[mg][n0][0];
                s[mg][n0][1] = __expf(s[mg][n0][1] - mnA[mg]); sumA[mg] += s[mg][n0][1];
                s[mg][n0][2] = __expf(s[mg][n0][2] - mnB[mg]); sumB[mg] += s[mg][n0][2];
                s[mg][n0][3] = __expf(s[mg][n0][3] - mnB[mg]); sumB[mg] += s[mg][n0][3];
                s[mg][n1][0] = __expf(s[mg][n1][0] - mnA[mg]); sumA[mg] += s[mg][n1][0];
                s[mg][n1][1] = __expf(s[mg][n1][1] - mnA[mg]); sumA[mg] += s[mg][n1][1];
                s[mg][n1][2] = __expf(s[mg][n1][2] - mnB[mg]); sumB[mg] += s[mg][n1][2];
                s[mg][n1][3] = __expf(s[mg][n1][3] - mnB[mg]); sumB[mg] += s[mg][n1][3];
                split2(s[mg][n0][0], s[mg][n0][1], ph[mg][0], pl[mg][0]);
                split2(s[mg][n0][2], s[mg][n0][3], ph[mg][1], pl[mg][1]);
                split2(s[mg][n1][0], s[mg][n1][1], ph[mg][2], pl[mg][2]);
                split2(s[mg][n1][2], s[mg][n1][3], ph[mg][3], pl[mg][3]);
            }
#pragma unroll
            for (int np = 0; np < 8; np++) {
                if (kk == 0) {
#pragma unroll
                    for (int mg = 0; mg < 2; mg++) {
                        o[mg][2*np][0]   *= fAv[mg]; o[mg][2*np][1]   *= fAv[mg];
                        o[mg][2*np][2]   *= fBv[mg]; o[mg][2*np][3]   *= fBv[mg];
                        o[mg][2*np+1][0] *= fAv[mg]; o[mg][2*np+1][1] *= fAv[mg];
                        o[mg][2*np+1][2] *= fBv[mg]; o[mg][2*np+1][3] *= fBv[mg];
                    }
                }
                uint32_t bvh[4], bvl[4];
                ldmx4(bvh[0], bvh[1], bvh[2], bvh[3],
                      vsm + vb_off[np] + (((kk * 2 + b_k16) ^ vb_x[np]) << 4));
                ldmx4(bvl[0], bvl[1], bvl[2], bvl[3],
                      vsm + 128 * 128 + vb_off[np] + (((kk * 2 + b_k16) ^ vb_x[np]) << 4));
#pragma unroll
                for (int mg = 0; mg < 2; mg++) {
                    mma_bf16(o[mg][2*np],   ph[mg], bvh[0], bvh[1]);
                    mma_bf16(o[mg][2*np+1], ph[mg], bvh[2], bvh[3]);
                    mma_bf16(o[mg][2*np],   ph[mg], bvl[0], bvl[1]);
                    mma_bf16(o[mg][2*np+1], ph[mg], bvl[2], bvl[3]);
                    mma_bf16(o[mg][2*np],   pl[mg], bvh[0], bvh[1]);
                    mma_bf16(o[mg][2*np+1], pl[mg], bvh[2], bvh[3]);
                }
            }
        }

#pragma unroll
        for (int mg = 0; mg < 2; mg++) {
            sumA[mg] += __shfl_xor_sync(0xffffffffu, sumA[mg], 1);
            sumA[mg] += __shfl_xor_sync(0xffffffffu, sumA[mg], 2);
            sumB[mg] += __shfl_xor_sync(0xffffffffu, sumB[mg], 1);
            sumB[mg] += __shfl_xor_sync(0xffffffffu, sumB[mg], 2);
            mAr[mg] = mnA[mg]; mBr[mg] = mnB[mg];
            lAr[mg] = lAr[mg] * fAv[mg] + sumA[mg];
            lBr[mg] = lBr[mg] * fBv[mg] + sumB[mg];
        }

        __syncthreads();   // all reads of this KV stage done before next-iter loads
    }

    // epilogue: write hi/hi/lo split directly into ao3 [S][K3]
#pragma unroll
    for (int mg = 0; mg < 2; mg++) {
        const float iA = 1.f / lAr[mg], iB = 1.f / lBr[mg];
        const int row0 = qb * 128 + wid * 32 + mg * 16 + (lane >> 2);
        const int col0 = h * 128 + (lane & 3) * 2;
#pragma unroll
        for (int nt = 0; nt < 16; nt++) {
            float xA = o[mg][nt][0] * iA, yA = o[mg][nt][1] * iA;
            float xB = o[mg][nt][2] * iB, yB = o[mg][nt][3] * iB;
            uint32_t hA, loA, hB, loB;
            split2(xA, yA, hA, loA);
            split2(xB, yB, hB, loB);
            __nv_bfloat16* pA = ao3 + (size_t)row0 * K3 + col0 + nt * 8;
            __nv_bfloat16* pB = ao3 + (size_t)(row0 + 8) * K3 + col0 + nt * 8;
            *(uint32_t*)&pA[0]        = hA;
            *(uint32_t*)&pA[DIM]      = hA;
            *(uint32_t*)&pA[2 * DIM]  = loA;
            *(uint32_t*)&pB[0]        = hB;
            *(uint32_t*)&pB[DIM]      = hB;
            *(uint32_t*)&pB[2 * DIM]  = loB;
        }
    }
}

// ---------------- launch ----------------------------------------------------
extern "C" void kernel_launch(void* const* d_in, const int* in_sizes, int n_in,
                              void* d_out, int out_size)
{
    const float* x    = (const float*)d_in[0];
    const float* Wq   = (const float*)d_in[1];
    const float* bq   = (const float*)d_in[2];
    const float* Wk   = (const float*)d_in[3];
    const float* bk   = (const float*)d_in[4];
    const float* Wv   = (const float*)d_in[5];
    const float* bv   = (const float*)d_in[6];
    const float* Wo   = (const float*)d_in[7];
    const float* bo   = (const float*)d_in[8];
    const float* nqw  = (const float*)d_in[9];
    const float* nkw  = (const float*)d_in[10];
    const float* cosb = (const float*)d_in[11];
    const float* sinb = (const float*)d_in[12];
    const int*   seql = (const int*)d_in[13];
    float* out = (float*)d_out;

    float *qkv, *bias3;
    __nv_bfloat16 *x3, *ao3, *w3, *qsb, *ksb, *vtb;
    cudaGetSymbolAddress((void**)&qkv,   g_qkv);
    cudaGetSymbolAddress((void**)&bias3, g_bias3);
    cudaGetSymbolAddress((void**)&x3,    g_x3);
    cudaGetSymbolAddress((void**)&ao3,   g_ao3);
    cudaGetSymbolAddress((void**)&w3,    g_w3);
    cudaGetSymbolAddress((void**)&qsb,   g_qs);
    cudaGetSymbolAddress((void**)&ksb,   g_ks);
    cudaGetSymbolAddress((void**)&vtb,   g_vt);

    cudaFuncSetAttribute(gemm_mma_kernel, cudaFuncAttributeMaxDynamicSharedMemorySize, SMEM_G);
    cudaFuncSetAttribute(attn_mma_kernel, cudaFuncAttributeMaxDynamicSharedMemorySize, ATTN_SMEM);

    cvt_all_kernel<<<CVT_BLOCKS, 256>>>(x, Wq, Wk, Wv, Wo, x3, w3);
    bias3_kernel<<<(3 * DIM + 255) / 256, 256>>>(bq, bk, bv, bias3);

    gemm_mma_kernel<<<dim3(3 * DIM / GBN, S_LEN / GBM), 256, SMEM_G>>>(
        x3, w3, bias3, qkv, 3 * DIM);

    const float qscale = 0.08838834764831845f;   // 1/sqrt(128)
    rms2_rope_split_kernel<<<S_LEN, 256>>>(qkv, nqw, nkw, cosb, sinb, qsb, ksb, qscale);
    vsplit_t_kernel<<<dim3(S_LEN / 32, DIM / 32), 256>>>(qkv, vtb);

    attn_mma_kernel<<<dim3(S_LEN / 128, NH), ATH, ATTN_SMEM>>>(qsb, ksb, vtb, ao3, seql);

    gemm_mma_kernel<<<dim3(DIM / GBN, S_LEN / GBM), 256, SMEM_G>>>(
        ao3, w3 + 3 * (size_t)DIM * K3, bo, out, DIM);
}

// round 13
// speedup vs baseline: 1.0479x; 1.0479x over previous
#include <cuda_runtime.h>
#include <cuda_bf16.h>
#include <math.h>
#include <stdint.h>

#define S_LEN 3072
#define DIM   2048
#define NH    16
#define HD    128
#define K3    (3*DIM)   // 6144: [hi | hi | lo] x [hi | lo | hi]

// ---------------- scratch (device globals; no allocations allowed) ----------
__device__ __align__(16) float g_qkv[S_LEN * 3 * DIM];  // qkv; later reused as C0|C1
__device__ __align__(16) float g_bias3[3 * DIM];
__device__ __align__(16) __nv_bfloat16 g_x3 [S_LEN * K3];
__device__ __align__(16) __nv_bfloat16 g_ao3[S_LEN * K3];
__device__ __align__(16) __nv_bfloat16 g_w3 [4][DIM * K3];
__device__ __align__(16) __nv_bfloat16 g_qs [NH * S_LEN * 256]; // [h][s][hi128|lo128]
__device__ __align__(16) __nv_bfloat16 g_ks [NH * S_LEN * 256];
__device__ __align__(16) __nv_bfloat16 g_vt [NH * 256 * S_LEN]; // [h][d:hi,d+128:lo][s]

// ---------------- PTX helpers ----------------------------------------------
__device__ __forceinline__ uint32_t smem_u32(const void* p) {
    uint32_t a;
    asm("{ .reg .u64 t; cvta.to.shared.u64 t, %1; cvt.u32.u64 %0, t; }" : "=r"(a) : "l"(p));
    return a;
}
__device__ __forceinline__ void cp_async16(uint32_t saddr, const void* g) {
    asm volatile("cp.async.cg.shared.global [%0], [%1], 16;" :: "r"(saddr), "l"(g));
}
#define CP_COMMIT() asm volatile("cp.async.commit_group;" ::: "memory")
#define CP_WAIT2()  asm volatile("cp.async.wait_group 2;" ::: "memory")
#define CP_WAIT1()  asm volatile("cp.async.wait_group 1;" ::: "memory")
#define CP_WAIT0()  asm volatile("cp.async.wait_group 0;" ::: "memory")

__device__ __forceinline__ void ldmx4(uint32_t& r0, uint32_t& r1, uint32_t& r2, uint32_t& r3,
                                      uint32_t addr) {
    asm volatile("ldmatrix.sync.aligned.m8n8.x4.shared.b16 {%0,%1,%2,%3}, [%4];"
                 : "=r"(r0), "=r"(r1), "=r"(r2), "=r"(r3) : "r"(addr));
}
__device__ __forceinline__ void mma_bf16(float* c, const uint32_t* a, uint32_t b0, uint32_t b1) {
    asm volatile("mma.sync.aligned.m16n8k16.row.col.f32.bf16.bf16.f32 "
                 "{%0,%1,%2,%3}, {%4,%5,%6,%7}, {%8,%9}, {%0,%1,%2,%3};"
                 : "+f"(c[0]), "+f"(c[1]), "+f"(c[2]), "+f"(c[3])
                 : "r"(a[0]), "r"(a[1]), "r"(a[2]), "r"(a[3]), "r"(b0), "r"(b1));
}
__device__ __forceinline__ void split2(float a, float b, uint32_t& hi, uint32_t& lo) {
    __nv_bfloat16 ha = __float2bfloat16(a), hb = __float2bfloat16(b);
    __nv_bfloat16 la = __float2bfloat16(a - __bfloat162float(ha));
    __nv_bfloat16 lb = __float2bfloat16(b - __bfloat162float(hb));
    __nv_bfloat162 H; H.x = ha; H.y = hb;
    __nv_bfloat162 L; L.x = la; L.y = lb;
    hi = *reinterpret_cast<uint32_t*>(&H);
    lo = *reinterpret_cast<uint32_t*>(&L);
}

// ---------------- fused split-bf16 conversion: x + 4 weights (float4) -------
#define NXQ (S_LEN * DIM / 4)
#define NWQ (DIM * DIM / 4)
#define CVT_BLOCKS ((NXQ + 4 * NWQ) / 256)

__global__ __launch_bounds__(256)
void cvt_all_kernel(const float* __restrict__ x,
                    const float* __restrict__ Wq, const float* __restrict__ Wk,
                    const float* __restrict__ Wv, const float* __restrict__ Wo,
                    __nv_bfloat16* __restrict__ x3, __nv_bfloat16* __restrict__ w3)
{
    int p = blockIdx.x * 256 + threadIdx.x;
    const float* src;
    __nv_bfloat16* dst;
    int mode, lp;
    if (p < NXQ) {
        src = x; dst = x3; mode = 0; lp = p;
    } else {
        int q = (p - NXQ) >> 20;
        lp = (p - NXQ) & (NWQ - 1);
        src = (q == 0) ? Wq : (q == 1) ? Wk : (q == 2) ? Wv : Wo;
        dst = w3 + (size_t)q * DIM * K3;
        mode = 1;
    }
    int i = lp * 4;
    float4 v = *(const float4*)&src[i];
    uint32_t hi0, lo0, hi1, lo1;
    split2(v.x, v.y, hi0, lo0);
    split2(v.z, v.w, hi1, lo1);
    uint2 hip = {hi0, hi1};
    uint2 lop = {lo0, lo1};
    int row = i >> 11;
    int c   = i & 2047;
    __nv_bfloat16* base = dst + (size_t)row * K3 + c;
    if (mode == 0) {
        *(uint2*)&base[0]       = hip;
        *(uint2*)&base[DIM]     = hip;
        *(uint2*)&base[2 * DIM] = lop;
    } else {
        *(uint2*)&base[0]       = hip;
        *(uint2*)&base[DIM]     = lop;
        *(uint2*)&base[2 * DIM] = hip;
    }
}

__global__ __launch_bounds__(256)
void bias3_kernel(const float* __restrict__ bq, const float* __restrict__ bk,
                  const float* __restrict__ bv, float* __restrict__ dst)
{
    int i = blockIdx.x * 256 + threadIdx.x;
    if (i >= 3 * DIM) return;
    dst[i] = (i < DIM) ? bq[i] : (i < 2 * DIM ? bk[i - DIM] : bv[i - 2 * DIM]);
}

// ---------------- mma.sync GEMM: CTA 128x128, 3-stage cp.async, 2 CTA/SM ----
// kc0/kniter enable split-K; bias==nullptr -> raw partial store.
#define GBM 128
#define GBN 128
#define GBK 64
#define GSTAGES 3
#define TILE_B 16384
#define SMEM_G (GSTAGES * TILE_B * 2)   // 98304

__device__ __forceinline__ void g_load_stage(uint32_t sA, uint32_t sB,
    const __nv_bfloat16* __restrict__ A, const __nv_bfloat16* __restrict__ B,
    int bm, int bn, int kc, int tid)
{
#pragma unroll
    for (int i = 0; i < 4; i++) {
        int c = tid + i * 256;
        int row = c >> 3, cc = c & 7;
        cp_async16(sA + row * 128 + ((cc ^ (row & 7)) << 4),
                   A + (size_t)(bm + row) * K3 + kc + cc * 8);
    }
#pragma unroll
    for (int i = 0; i < 4; i++) {
        int c = tid + i * 256;
        int row = c >> 3, cc = c & 7;
        cp_async16(sB + row * 128 + ((cc ^ (row & 7)) << 4),
                   B + (size_t)(bn + row) * K3 + kc + cc * 8);
    }
}

__global__ __launch_bounds__(256, 2)
void gemm_mma_kernel(const __nv_bfloat16* __restrict__ A,
                     const __nv_bfloat16* __restrict__ B,
                     const float* __restrict__ bias, float* __restrict__ C, int Nn,
                     int kc0, int kniter)
{
    extern __shared__ __align__(1024) char smem[];
    const uint32_t sb = smem_u32(smem);
    const uint32_t sAb = sb;
    const uint32_t sBb = sb + GSTAGES * TILE_B;

    const int tid = threadIdx.x;
    const int wid = tid >> 5, lane = tid & 31;
    const int bm = blockIdx.y * GBM, bn = blockIdx.x * GBN;
    const int wm = (wid & 1) * 64;
    const int wn = (wid >> 1) * 32;

    const int a_row = lane & 15;
    const int a_kh  = (lane >> 4);
    const int b_row = (lane & 7) + ((lane >> 4) << 3);
    const int b_kh  = (lane >> 3) & 1;

    float acc[4][4][4];
#pragma unroll
    for (int mt = 0; mt < 4; mt++)
#pragma unroll
        for (int nt = 0; nt < 4; nt++)
#pragma unroll
            for (int r = 0; r < 4; r++) acc[mt][nt][r] = 0.f;

#pragma unroll
    for (int s = 0; s < GSTAGES - 1; s++) {
        g_load_stage(sAb + s * TILE_B, sBb + s * TILE_B, A, B, bm, bn, kc0 + s * GBK, tid);
        CP_COMMIT();
    }

    uint32_t a_base[4], b_base[2]; int a_xm[4], b_xm[2];
#pragma unroll
    for (int mt = 0; mt < 4; mt++) {
        int row = wm + mt * 16 + a_row;
        a_base[mt] = row * 128;
        a_xm[mt] = row & 7;
    }
#pragma unroll
    for (int np = 0; np < 2; np++) {
        int row = wn + np * 16 + b_row;
        b_base[np] = row * 128;
        b_xm[np] = row & 7;
    }

    int cs = 0, ls = GSTAGES - 1;
    for (int it = 0; it < kniter; it++) {
        CP_WAIT1();
        __syncthreads();
        const uint32_t sA = sAb + cs * TILE_B;
        const uint32_t sB = sBb + cs * TILE_B;

#pragma unroll
        for (int ks = 0; ks < 4; ks++) {
            uint32_t af[4][4];
#pragma unroll
            for (int mt = 0; mt < 4; mt++)
                ldmx4(af[mt][0], af[mt][1], af[mt][2], af[mt][3],
                      sA + a_base[mt] + (((ks * 2 + a_kh) ^ a_xm[mt]) << 4));
            uint32_t bfr[2][4];
#pragma unroll
            for (int np = 0; np < 2; np++)
                ldmx4(bfr[np][0], bfr[np][1], bfr[np][2], bfr[np][3],
                      sB + b_base[np] + (((ks * 2 + b_kh) ^ b_xm[np]) << 4));
#pragma unroll
            for (int mt = 0; mt < 4; mt++)
#pragma unroll
                for (int nt = 0; nt < 4; nt++)
                    mma_bf16(acc[mt][nt], af[mt],
                             bfr[nt >> 1][(nt & 1) * 2], bfr[nt >> 1][(nt & 1) * 2 + 1]);
        }

        const int li = it + GSTAGES - 1;
        if (li < kniter)
            g_load_stage(sAb + ls * TILE_B, sBb + ls * TILE_B, A, B, bm, bn,
                         kc0 + li * GBK, tid);
        CP_COMMIT();
        cs = (cs + 1 == GSTAGES) ? 0 : cs + 1;
        ls = (ls + 1 == GSTAGES) ? 0 : ls + 1;
    }

    const int tq = lane >> 2, tr4 = lane & 3;
#pragma unroll
    for (int mt = 0; mt < 4; mt++) {
#pragma unroll
        for (int nt = 0; nt < 4; nt++) {
            const int row = bm + wm + mt * 16 + tq;
            const int col = bn + wn + nt * 8 + tr4 * 2;
            float b0 = 0.f, b1 = 0.f;
            if (bias) { b0 = bias[col]; b1 = bias[col + 1]; }
            float2 v0 = {acc[mt][nt][0] + b0, acc[mt][nt][1] + b1};
            float2 v1 = {acc[mt][nt][2] + b0, acc[mt][nt][3] + b1};
            *(float2*)&C[(size_t)row * Nn + col]       = v0;
            *(float2*)&C[(size_t)(row + 8) * Nn + col] = v1;
        }
    }
}

// ---------------- split-K reduction: out = C0 + C1 + bias -------------------
__global__ __launch_bounds__(256)
void reduce2_kernel(const float* __restrict__ C0, const float* __restrict__ C1,
                    const float* __restrict__ bias, float* __restrict__ out)
{
    int i = (blockIdx.x * 256 + threadIdx.x) * 4;
    float4 a = *(const float4*)&C0[i];
    float4 b = *(const float4*)&C1[i];
    const float4 bb = *(const float4*)&bias[i & 2047];
    float4 r = {a.x + b.x + bb.x, a.y + b.y + bb.y,
                a.z + b.z + bb.z, a.w + b.w + bb.w};
    *(float4*)&out[i] = r;
}

// ---------------- fused RMSNorm+RoPE+split for q AND k ----------------------
__global__ __launch_bounds__(256)
void rms2_rope_split_kernel(const float* __restrict__ qkv,
                            const float* __restrict__ wq, const float* __restrict__ wk,
                            const float* __restrict__ cosb, const float* __restrict__ sinb,
                            __nv_bfloat16* __restrict__ qs, __nv_bfloat16* __restrict__ ks,
                            float qscale)
{
    const int row = blockIdx.x;
    const float* pq = qkv + (size_t)row * (3 * DIM);
    const float* pk = pq + DIM;
    const int tid = threadIdx.x;

    float ssq = 0.f, ssk = 0.f;
    for (int i = tid; i < DIM; i += 256) {
        float a = pq[i]; ssq += a * a;
        float b = pk[i]; ssk += b * b;
    }
#pragma unroll
    for (int off = 16; off > 0; off >>= 1) {
        ssq += __shfl_xor_sync(0xffffffffu, ssq, off);
        ssk += __shfl_xor_sync(0xffffffffu, ssk, off);
    }
    __shared__ float redq[8], redk[8];
    __shared__ float scq_s, sck_s;
    if ((tid & 31) == 0) { redq[tid >> 5] = ssq; redk[tid >> 5] = ssk; }
    __syncthreads();
    if (tid == 0) {
        float tq = 0.f, tk = 0.f;
#pragma unroll
        for (int i = 0; i < 8; i++) { tq += redq[i]; tk += redk[i]; }
        scq_s = rsqrtf(tq / (float)DIM + 1e-6f);
        sck_s = rsqrtf(tk / (float)DIM + 1e-6f);
    }
    __syncthreads();
    const float scq = scq_s, sck = sck_s;

    const float* crow = cosb + (size_t)row * HD;
    const float* srow = sinb + (size_t)row * HD;
    for (int pi = tid; pi < DIM / 2; pi += 256) {
        int i0 = 2 * pi;
        int h = i0 >> 7;
        int d = i0 & (HD - 1);
        float c = crow[d], s = srow[d];
        {
            float2 xv = *(const float2*)&pq[i0];
            float e = xv.x * scq * wq[i0];
            float o = xv.y * scq * wq[i0 + 1];
            float rx = (e * c - o * s) * qscale;
            float ry = (o * c + e * s) * qscale;
            uint32_t hi, lo;
            split2(rx, ry, hi, lo);
            __nv_bfloat16* base = qs + (size_t)h * S_LEN * 256 + (size_t)row * 256;
            *(uint32_t*)&base[d]       = hi;
            *(uint32_t*)&base[128 + d] = lo;
        }
        {
            float2 xv = *(const float2*)&pk[i0];
            float e = xv.x * sck * wk[i0];
            float o = xv.y * sck * wk[i0 + 1];
            float rx = e * c - o * s;
            float ry = o * c + e * s;
            uint32_t hi, lo;
            split2(rx, ry, hi, lo);
            __nv_bfloat16* base = ks + (size_t)h * S_LEN * 256 + (size_t)row * 256;
            *(uint32_t*)&base[d]       = hi;
            *(uint32_t*)&base[128 + d] = lo;
        }
    }
}

// ---------------- V transpose + split -> [NH][256][S], 4B stores ------------
__global__ __launch_bounds__(256)
void vsplit_t_kernel(const float* __restrict__ qkv, __nv_bfloat16* __restrict__ vt)
{
    __shared__ float tile[32][33];
    const int s0 = blockIdx.x * 32;
    const int c0 = blockIdx.y * 32;
    const int tx = threadIdx.x & 31;
    const int ty = threadIdx.x >> 5;

#pragma unroll
    for (int i = 0; i < 4; i++) {
        int r = ty + i * 8;
        tile[r][tx] = qkv[(size_t)(s0 + r) * (3 * DIM) + 2 * DIM + c0 + tx];
    }
    __syncthreads();
    const int sx = (threadIdx.x & 15) * 2;
    const int dr0 = threadIdx.x >> 4;
#pragma unroll
    for (int i = 0; i < 2; i++) {
        int dr = dr0 + i * 16;
        int dg = c0 + dr;
        int h = dg >> 7, d = dg & 127;
        float v0 = tile[sx][dr];
        float v1 = tile[sx + 1][dr];
        uint32_t hi, lo;
        split2(v0, v1, hi, lo);
        size_t base = (size_t)h * 256 * S_LEN;
        *(uint32_t*)&vt[base + (size_t)d * S_LEN + s0 + sx]         = hi;
        *(uint32_t*)&vt[base + (size_t)(d + 128) * S_LEN + s0 + sx] = lo;
    }
}

// ---------------- tensor-core flash attention (R11: chunked softmax/PV) -----
#define K_SM_BYTES  (64 * 512)
#define V_SM_BYTES  (256 * 128)
#define KV_ST       (K_SM_BYTES + V_SM_BYTES)
#define ATTN_SMEM   (3 * KV_ST)

__device__ __forceinline__ void attn_load_kv(uint32_t kvb,
    const __nv_bfloat16* __restrict__ ksrc0, const __nv_bfloat16* __restrict__ vsrc0,
    int kt, int tid)
{
    const __nv_bfloat16* ksrc = ksrc0 + (size_t)kt * 64 * 256;
#pragma unroll
    for (int u = 0; u < 8; u++) {
        int c = tid + u * 256;
        int r = c >> 5, ch = c & 31;
        cp_async16(kvb + r * 512 + ((ch ^ (r & 7)) << 4), ksrc + (size_t)r * 256 + ch * 8);
    }
    const __nv_bfloat16* vsrc = vsrc0 + kt * 64;
    const uint32_t vb = kvb + K_SM_BYTES;
#pragma unroll
    for (int u = 0; u < 8; u++) {
        int c = tid + u * 256;
        int r = c >> 3, ch = c & 7;
        cp_async16(vb + r * 128 + ((ch ^ (r & 7)) << 4), vsrc + (size_t)r * S_LEN + ch * 8);
    }
}

__global__ __launch_bounds__(256, 1)
void attn_mma_kernel(const __nv_bfloat16* __restrict__ qs,
                     const __nv_bfloat16* __restrict__ ks,
                     const __nv_bfloat16* __restrict__ vt,
                     __nv_bfloat16* __restrict__ ao3, const int* __restrict__ seq_lens)
{
    extern __shared__ __align__(1024) char smem[];
    const uint32_t sb = smem_u32(smem);
    const int tid = threadIdx.x, lane = tid & 31, wid = tid >> 5;
    const int qb = blockIdx.x, h = blockIdx.y;

    const int seqlen = seq_lens[0];
    const int ntiles = (seqlen + 63) >> 6;

    const __nv_bfloat16* qsrc  = qs + ((size_t)h * S_LEN + qb * 128) * 256;
    const __nv_bfloat16* ksrc0 = ks + (size_t)h * S_LEN * 256;
    const __nv_bfloat16* vsrc0 = vt + (size_t)h * 256 * S_LEN;

    const uint32_t qtmp = sb + 2 * KV_ST;
#pragma unroll
    for (int u = 0; u < 16; u++) {
        int c = tid + u * 256;
        int r = c >> 5, ch = c & 31;
        cp_async16(qtmp + r * 512 + ((ch ^ (r & 7)) << 4), qsrc + (size_t)r * 256 + ch * 8);
    }
    CP_COMMIT();
    attn_load_kv(sb, ksrc0, vsrc0, 0, tid);
    CP_COMMIT();
    CP_WAIT1();
    __syncthreads();

    const int a_row = wid * 16 + (lane & 15);
    const uint32_t a_off = a_row * 512;
    const int a_x = a_row & 7;
    const int a_k16 = lane >> 4;
    uint32_t qh[8][4], ql[8][4];
#pragma unroll
    for (int kst = 0; kst < 8; kst++) {
        ldmx4(qh[kst][0], qh[kst][1], qh[kst][2], qh[kst][3],
              qtmp + a_off + (((kst * 2 + a_k16) ^ a_x) << 4));
        ldmx4(ql[kst][0], ql[kst][1], ql[kst][2], ql[kst][3],
              qtmp + a_off + (((16 + kst * 2 + a_k16) ^ a_x) << 4));
    }
    __syncthreads();

    if (ntiles > 1) {
        attn_load_kv(sb + KV_ST, ksrc0, vsrc0, 1, tid);
        CP_COMMIT();
    }

    const int b_row = (lane & 7) + ((lane >> 4) << 3);
    const int b_k16 = (lane >> 3) & 1;

    uint32_t kb_off[4]; int kb_x[4];
#pragma unroll
    for (int np = 0; np < 4; np++) {
        int row = np * 16 + b_row;
        kb_off[np] = row * 512; kb_x[np] = row & 7;
    }
    uint32_t vb_off[8]; int vb_x[8];
#pragma unroll
    for (int np = 0; np < 8; np++) {
        int row = np * 16 + b_row;
        vb_off[np] = row * 128; vb_x[np] = row & 7;
    }

    float o[16][4];
#pragma unroll
    for (int nt = 0; nt < 16; nt++)
#pragma unroll
        for (int c = 0; c < 4; c++) o[nt][c] = 0.f;
    float mA = -1e30f, mB = -1e30f, lA = 0.f, lB = 0.f;

    int stg = 0;
    for (int kt = 0; kt < ntiles; kt++) {
        if (kt + 2 < ntiles) {
            int ps = stg + 2; if (ps >= 3) ps -= 3;
            attn_load_kv(sb + ps * KV_ST, ksrc0, vsrc0, kt + 2, tid);
            CP_COMMIT();
        }
        const int na = ntiles - 1 - kt;
        if (na >= 2)      { CP_WAIT2(); }
        else if (na == 1) { CP_WAIT1(); }
        else              { CP_WAIT0(); }
        __syncthreads();
        const uint32_t ksm = sb + stg * KV_ST;
        const uint32_t vsm = ksm + K_SM_BYTES;

        float s[8][4];
#pragma unroll
        for (int nt = 0; nt < 8; nt++)
#pragma unroll
            for (int c = 0; c < 4; c++) s[nt][c] = 0.f;

#pragma unroll
        for (int kst = 0; kst < 8; kst++) {
#pragma unroll
            for (int np = 0; np < 4; np++) {
                uint32_t bh[4], bl[4];
                ldmx4(bh[0], bh[1], bh[2], bh[3],
                      ksm + kb_off[np] + (((kst * 2 + b_k16) ^ kb_x[np]) << 4));
                ldmx4(bl[0], bl[1], bl[2], bl[3],
                      ksm + kb_off[np] + (((16 + kst * 2 + b_k16) ^ kb_x[np]) << 4));
                mma_bf16(s[2*np],   qh[kst], bh[0], bh[1]);
                mma_bf16(s[2*np+1], qh[kst], bh[2], bh[3]);
                mma_bf16(s[2*np],   qh[kst], bl[0], bl[1]);
                mma_bf16(s[2*np+1], qh[kst], bl[2], bl[3]);
                mma_bf16(s[2*np],   ql[kst], bh[0], bh[1]);
                mma_bf16(s[2*np+1], ql[kst], bh[2], bh[3]);
            }
        }

        if (kt * 64 + 64 > seqlen) {
            const int kbase = kt * 64 + (lane & 3) * 2;
#pragma unroll
            for (int nt = 0; nt < 8; nt++)
#pragma unroll
                for (int c = 0; c < 4; c++) {
                    int gk = kbase + nt * 8 + (c & 1);
                    if (gk >= seqlen) s[nt][c] = -1e30f;
                }
        }

        float pmA = -1e30f, pmB = -1e30f;
#pragma unroll
        for (int nt = 0; nt < 8; nt++) {
            pmA = fmaxf(pmA, fmaxf(s[nt][0], s[nt][1]));
            pmB = fmaxf(pmB, fmaxf(s[nt][2], s[nt][3]));
        }
        pmA = fmaxf(pmA, __shfl_xor_sync(0xffffffffu, pmA, 1));
        pmA = fmaxf(pmA, __shfl_xor_sync(0xffffffffu, pmA, 2));
        pmB = fmaxf(pmB, __shfl_xor_sync(0xffffffffu, pmB, 1));
        pmB = fmaxf(pmB, __shfl_xor_sync(0xffffffffu, pmB, 2));

        const float mnA = fmaxf(mA, pmA), mnB = fmaxf(mB, pmB);
        const float fA = __expf(mA - mnA), fB = __expf(mB - mnB);
        float sumA = 0.f, sumB = 0.f;

#pragma unroll
        for (int kk = 0; kk < 4; kk++) {
            const int n0 = 2 * kk, n1 = 2 * kk + 1;
            s[n0][0] = __expf(s[n0][0] - mnA); sumA += s[n0][0];
            s[n0][1] = __expf(s[n0][1] - mnA); sumA += s[n0][1];
            s[n0][2] = __expf(s[n0][2] - mnB); sumB += s[n0][2];
            s[n0][3] = __expf(s[n0][3] - mnB); sumB += s[n0][3];
            s[n1][0] = __expf(s[n1][0] - mnA); sumA += s[n1][0];
            s[n1][1] = __expf(s[n1][1] - mnA); sumA += s[n1][1];
            s[n1][2] = __expf(s[n1][2] - mnB); sumB += s[n1][2];
            s[n1][3] = __expf(s[n1][3] - mnB); sumB += s[n1][3];

            uint32_t ph[4], pl[4];
            split2(s[n0][0], s[n0][1], ph[0], pl[0]);
            split2(s[n0][2], s[n0][3], ph[1], pl[1]);
            split2(s[n1][0], s[n1][1], ph[2], pl[2]);
            split2(s[n1][2], s[n1][3], ph[3], pl[3]);

#pragma unroll
            for (int np = 0; np < 8; np++) {
                if (kk == 0) {
                    o[2*np][0]   *= fA; o[2*np][1]   *= fA;
                    o[2*np][2]   *= fB; o[2*np][3]   *= fB;
                    o[2*np+1][0] *= fA; o[2*np+1][1] *= fA;
                    o[2*np+1][2] *= fB; o[2*np+1][3] *= fB;
                }
                uint32_t bvh[4], bvl[4];
                ldmx4(bvh[0], bvh[1], bvh[2], bvh[3],
                      vsm + vb_off[np] + (((kk * 2 + b_k16) ^ vb_x[np]) << 4));
                ldmx4(bvl[0], bvl[1], bvl[2], bvl[3],
                      vsm + 128 * 128 + vb_off[np] + (((kk * 2 + b_k16) ^ vb_x[np]) << 4));
                mma_bf16(o[2*np],   ph, bvh[0], bvh[1]);
                mma_bf16(o[2*np+1], ph, bvh[2], bvh[3]);
                mma_bf16(o[2*np],   ph, bvl[0], bvl[1]);
                mma_bf16(o[2*np+1], ph, bvl[2], bvl[3]);
                mma_bf16(o[2*np],   pl, bvh[0], bvh[1]);
                mma_bf16(o[2*np+1], pl, bvh[2], bvh[3]);
            }
        }

        sumA += __shfl_xor_sync(0xffffffffu, sumA, 1);
        sumA += __shfl_xor_sync(0xffffffffu, sumA, 2);
        sumB += __shfl_xor_sync(0xffffffffu, sumB, 1);
        sumB += __shfl_xor_sync(0xffffffffu, sumB, 2);
        mA = mnA; mB = mnB;
        lA = lA * fA + sumA;
        lB = lB * fB + sumB;

        __syncthreads();
        stg = (stg + 1 == 3) ? 0 : stg + 1;
    }

    const float iA = 1.f / lA, iB = 1.f / lB;
    const int row0 = qb * 128 + wid * 16 + (lane >> 2);
    const int col0 = h * 128 + (lane & 3) * 2;
#pragma unroll
    for (int nt = 0; nt < 16; nt++) {
        float xA = o[nt][0] * iA, yA = o[nt][1] * iA;
        float xB = o[nt][2] * iB, yB = o[nt][3] * iB;
        uint32_t hA, loA, hB, loB;
        split2(xA, yA, hA, loA);
        split2(xB, yB, hB, loB);
        __nv_bfloat16* pA = ao3 + (size_t)row0 * K3 + col0 + nt * 8;
        __nv_bfloat16* pB = ao3 + (size_t)(row0 + 8) * K3 + col0 + nt * 8;
        *(uint32_t*)&pA[0]        = hA;
        *(uint32_t*)&pA[DIM]      = hA;
        *(uint32_t*)&pA[2 * DIM]  = loA;
        *(uint32_t*)&pB[0]        = hB;
        *(uint32_t*)&pB[DIM]      = hB;
        *(uint32_t*)&pB[2 * DIM]  = loB;
    }
}

// ---------------- launch ----------------------------------------------------
extern "C" void kernel_launch(void* const* d_in, const int* in_sizes, int n_in,
                              void* d_out, int out_size)
{
    const float* x    = (const float*)d_in[0];
    const float* Wq   = (const float*)d_in[1];
    const float* bq   = (const float*)d_in[2];
    const float* Wk   = (const float*)d_in[3];
    const float* bk   = (const float*)d_in[4];
    const float* Wv   = (const float*)d_in[5];
    const float* bv   = (const float*)d_in[6];
    const float* Wo   = (const float*)d_in[7];
    const float* bo   = (const float*)d_in[8];
    const float* nqw  = (const float*)d_in[9];
    const float* nkw  = (const float*)d_in[10];
    const float* cosb = (const float*)d_in[11];
    const float* sinb = (const float*)d_in[12];
    const int*   seql = (const int*)d_in[13];
    float* out = (float*)d_out;

    float *qkv, *bias3;
    __nv_bfloat16 *x3, *ao3, *w3, *qsb, *ksb, *vtb;
    cudaGetSymbolAddress((void**)&qkv,   g_qkv);
    cudaGetSymbolAddress((void**)&bias3, g_bias3);
    cudaGetSymbolAddress((void**)&x3,    g_x3);
    cudaGetSymbolAddress((void**)&ao3,   g_ao3);
    cudaGetSymbolAddress((void**)&w3,    g_w3);
    cudaGetSymbolAddress((void**)&qsb,   g_qs);
    cudaGetSymbolAddress((void**)&ksb,   g_ks);
    cudaGetSymbolAddress((void**)&vtb,   g_vt);

    cudaFuncSetAttribute(gemm_mma_kernel, cudaFuncAttributeMaxDynamicSharedMemorySize, SMEM_G);
    cudaFuncSetAttribute(attn_mma_kernel, cudaFuncAttributeMaxDynamicSharedMemorySize, ATTN_SMEM);

    cvt_all_kernel<<<CVT_BLOCKS, 256>>>(x, Wq, Wk, Wv, Wo, x3, w3);
    bias3_kernel<<<(3 * DIM + 255) / 256, 256>>>(bq, bk, bv, bias3);

    // fused QKV projection (full-K, bias)
    gemm_mma_kernel<<<dim3(3 * DIM / GBN, S_LEN / GBM), 256, SMEM_G>>>(
        x3, w3, bias3, qkv, 3 * DIM, 0, K3 / GBK);

    const float qscale = 0.08838834764831845f;   // 1/sqrt(128)
    rms2_rope_split_kernel<<<S_LEN, 256>>>(qkv, nqw, nkw, cosb, sinb, qsb, ksb, qscale);
    vsplit_t_kernel<<<dim3(S_LEN / 32, DIM / 32), 256>>>(qkv, vtb);

    attn_mma_kernel<<<dim3(S_LEN / 128, NH), 256, ATTN_SMEM>>>(qsb, ksb, vtb, ao3, seql);

    // output projection, split-K2: g_qkv (now dead) holds partials C0|C1
    float* C0 = qkv;
    float* C1 = qkv + (size_t)S_LEN * DIM;
    const __nv_bfloat16* Bo = w3 + 3 * (size_t)DIM * K3;
    gemm_mma_kernel<<<dim3(DIM / GBN, S_LEN / GBM), 256, SMEM_G>>>(
        ao3, Bo, nullptr, C0, DIM, 0, K3 / (2 * GBK));
    gemm_mma_kernel<<<dim3(DIM / GBN, S_LEN / GBM), 256, SMEM_G>>>(
        ao3, Bo, nullptr, C1, DIM, K3 / 2, K3 / (2 * GBK));
    reduce2_kernel<<<S_LEN * DIM / 4 / 256, 256>>>(C0, C1, bo, out);
}

// round 14
// speedup vs baseline: 1.0576x; 1.0093x over previous
#include <cuda_runtime.h>
#include <cuda_bf16.h>
#include <math.h>
#include <stdint.h>

#define S_LEN 3072
#define DIM   2048
#define NH    16
#define HD    128
#define K3    (3*DIM)   // 6144: [hi | hi | lo] x [hi | lo | hi]

// ---------------- scratch (device globals; no allocations allowed) ----------
__device__ __align__(16) float g_qkv[S_LEN * 3 * DIM];  // qkv; later reused as C0|C1
__device__ __align__(16) float g_bias3[3 * DIM];
__device__ __align__(16) __nv_bfloat16 g_x3 [S_LEN * K3];
__device__ __align__(16) __nv_bfloat16 g_ao3[S_LEN * K3];
__device__ __align__(16) __nv_bfloat16 g_w3 [4][DIM * K3];
__device__ __align__(16) __nv_bfloat16 g_qs [NH * S_LEN * 256]; // [h][s][hi128|lo128]
__device__ __align__(16) __nv_bfloat16 g_ks [NH * S_LEN * 256];
__device__ __align__(16) __nv_bfloat16 g_vt [NH * 256 * S_LEN]; // [h][d:hi,d+128:lo][s]

// ---------------- PTX helpers ----------------------------------------------
__device__ __forceinline__ uint32_t smem_u32(const void* p) {
    uint32_t a;
    asm("{ .reg .u64 t; cvta.to.shared.u64 t, %1; cvt.u32.u64 %0, t; }" : "=r"(a) : "l"(p));
    return a;
}
__device__ __forceinline__ void cp_async16(uint32_t saddr, const void* g) {
    asm volatile("cp.async.cg.shared.global [%0], [%1], 16;" :: "r"(saddr), "l"(g));
}
#define CP_COMMIT() asm volatile("cp.async.commit_group;" ::: "memory")
#define CP_WAIT2()  asm volatile("cp.async.wait_group 2;" ::: "memory")
#define CP_WAIT1()  asm volatile("cp.async.wait_group 1;" ::: "memory")
#define CP_WAIT0()  asm volatile("cp.async.wait_group 0;" ::: "memory")

__device__ __forceinline__ void ldmx4(uint32_t& r0, uint32_t& r1, uint32_t& r2, uint32_t& r3,
                                      uint32_t addr) {
    asm volatile("ldmatrix.sync.aligned.m8n8.x4.shared.b16 {%0,%1,%2,%3}, [%4];"
                 : "=r"(r0), "=r"(r1), "=r"(r2), "=r"(r3) : "r"(addr));
}
__device__ __forceinline__ void mma_bf16(float* c, const uint32_t* a, uint32_t b0, uint32_t b1) {
    asm volatile("mma.sync.aligned.m16n8k16.row.col.f32.bf16.bf16.f32 "
                 "{%0,%1,%2,%3}, {%4,%5,%6,%7}, {%8,%9}, {%0,%1,%2,%3};"
                 : "+f"(c[0]), "+f"(c[1]), "+f"(c[2]), "+f"(c[3])
                 : "r"(a[0]), "r"(a[1]), "r"(a[2]), "r"(a[3]), "r"(b0), "r"(b1));
}
__device__ __forceinline__ void split2(float a, float b, uint32_t& hi, uint32_t& lo) {
    __nv_bfloat16 ha = __float2bfloat16(a), hb = __float2bfloat16(b);
    __nv_bfloat16 la = __float2bfloat16(a - __bfloat162float(ha));
    __nv_bfloat16 lb = __float2bfloat16(b - __bfloat162float(hb));
    __nv_bfloat162 H; H.x = ha; H.y = hb;
    __nv_bfloat162 L; L.x = la; L.y = lb;
    hi = *reinterpret_cast<uint32_t*>(&H);
    lo = *reinterpret_cast<uint32_t*>(&L);
}

// ---------------- fused split-bf16 conversion: x + 4 weights (float4) -------
#define NXQ (S_LEN * DIM / 4)
#define NWQ (DIM * DIM / 4)
#define CVT_BLOCKS ((NXQ + 4 * NWQ) / 256)

__global__ __launch_bounds__(256)
void cvt_all_kernel(const float* __restrict__ x,
                    const float* __restrict__ Wq, const float* __restrict__ Wk,
                    const float* __restrict__ Wv, const float* __restrict__ Wo,
                    __nv_bfloat16* __restrict__ x3, __nv_bfloat16* __restrict__ w3)
{
    int p = blockIdx.x * 256 + threadIdx.x;
    const float* src;
    __nv_bfloat16* dst;
    int mode, lp;
    if (p < NXQ) {
        src = x; dst = x3; mode = 0; lp = p;
    } else {
        int q = (p - NXQ) >> 20;
        lp = (p - NXQ) & (NWQ - 1);
        src = (q == 0) ? Wq : (q == 1) ? Wk : (q == 2) ? Wv : Wo;
        dst = w3 + (size_t)q * DIM * K3;
        mode = 1;
    }
    int i = lp * 4;
    float4 v = *(const float4*)&src[i];
    uint32_t hi0, lo0, hi1, lo1;
    split2(v.x, v.y, hi0, lo0);
    split2(v.z, v.w, hi1, lo1);
    uint2 hip = {hi0, hi1};
    uint2 lop = {lo0, lo1};
    int row = i >> 11;
    int c   = i & 2047;
    __nv_bfloat16* base = dst + (size_t)row * K3 + c;
    if (mode == 0) {
        *(uint2*)&base[0]       = hip;
        *(uint2*)&base[DIM]     = hip;
        *(uint2*)&base[2 * DIM] = lop;
    } else {
        *(uint2*)&base[0]       = hip;
        *(uint2*)&base[DIM]     = lop;
        *(uint2*)&base[2 * DIM] = hip;
    }
}

__global__ __launch_bounds__(256)
void bias3_kernel(const float* __restrict__ bq, const float* __restrict__ bk,
                  const float* __restrict__ bv, float* __restrict__ dst)
{
    int i = blockIdx.x * 256 + threadIdx.x;
    if (i >= 3 * DIM) return;
    dst[i] = (i < DIM) ? bq[i] : (i < 2 * DIM ? bk[i - DIM] : bv[i - 2 * DIM]);
}

// ---------------- mma.sync GEMM: CTA 128x128, 3-stage cp.async, 2 CTA/SM ----
// blockIdx.z selects split-K slice (kc0 = z*ksplit*GBK, C += z*Cstride).
#define GBM 128
#define GBN 128
#define GBK 64
#define GSTAGES 3
#define TILE_B 16384
#define SMEM_G (GSTAGES * TILE_B * 2)   // 98304

__device__ __forceinline__ void g_load_stage(uint32_t sA, uint32_t sB,
    const __nv_bfloat16* __restrict__ A, const __nv_bfloat16* __restrict__ B,
    int bm, int bn, int kc, int tid)
{
#pragma unroll
    for (int i = 0; i < 4; i++) {
        int c = tid + i * 256;
        int row = c >> 3, cc = c & 7;
        cp_async16(sA + row * 128 + ((cc ^ (row & 7)) << 4),
                   A + (size_t)(bm + row) * K3 + kc + cc * 8);
    }
#pragma unroll
    for (int i = 0; i < 4; i++) {
        int c = tid + i * 256;
        int row = c >> 3, cc = c & 7;
        cp_async16(sB + row * 128 + ((cc ^ (row & 7)) << 4),
                   B + (size_t)(bn + row) * K3 + kc + cc * 8);
    }
}

__global__ __launch_bounds__(256, 2)
void gemm_mma_kernel(const __nv_bfloat16* __restrict__ A,
                     const __nv_bfloat16* __restrict__ B,
                     const float* __restrict__ bias, float* __restrict__ C, int Nn,
                     int kniter, size_t Cstride)
{
    extern __shared__ __align__(1024) char smem[];
    const uint32_t sb = smem_u32(smem);
    const uint32_t sAb = sb;
    const uint32_t sBb = sb + GSTAGES * TILE_B;

    const int tid = threadIdx.x;
    const int wid = tid >> 5, lane = tid & 31;
    const int bm = blockIdx.y * GBM, bn = blockIdx.x * GBN;
    const int kc0 = blockIdx.z * kniter * GBK;
    C += (size_t)blockIdx.z * Cstride;
    const int wm = (wid & 1) * 64;
    const int wn = (wid >> 1) * 32;

    const int a_row = lane & 15;
    const int a_kh  = (lane >> 4);
    const int b_row = (lane & 7) + ((lane >> 4) << 3);
    const int b_kh  = (lane >> 3) & 1;

    float acc[4][4][4];
#pragma unroll
    for (int mt = 0; mt < 4; mt++)
#pragma unroll
        for (int nt = 0; nt < 4; nt++)
#pragma unroll
            for (int r = 0; r < 4; r++) acc[mt][nt][r] = 0.f;

#pragma unroll
    for (int s = 0; s < GSTAGES - 1; s++) {
        g_load_stage(sAb + s * TILE_B, sBb + s * TILE_B, A, B, bm, bn, kc0 + s * GBK, tid);
        CP_COMMIT();
    }

    uint32_t a_base[4], b_base[2]; int a_xm[4], b_xm[2];
#pragma unroll
    for (int mt = 0; mt < 4; mt++) {
        int row = wm + mt * 16 + a_row;
        a_base[mt] = row * 128;
        a_xm[mt] = row & 7;
    }
#pragma unroll
    for (int np = 0; np < 2; np++) {
        int row = wn + np * 16 + b_row;
        b_base[np] = row * 128;
        b_xm[np] = row & 7;
    }

    int cs = 0, ls = GSTAGES - 1;
    for (int it = 0; it < kniter; it++) {
        CP_WAIT1();
        __syncthreads();
        const uint32_t sA = sAb + cs * TILE_B;
        const uint32_t sB = sBb + cs * TILE_B;

#pragma unroll
        for (int ks = 0; ks < 4; ks++) {
            uint32_t af[4][4];
#pragma unroll
            for (int mt = 0; mt < 4; mt++)
                ldmx4(af[mt][0], af[mt][1], af[mt][2], af[mt][3],
                      sA + a_base[mt] + (((ks * 2 + a_kh) ^ a_xm[mt]) << 4));
            uint32_t bfr[2][4];
#pragma unroll
            for (int np = 0; np < 2; np++)
                ldmx4(bfr[np][0], bfr[np][1], bfr[np][2], bfr[np][3],
                      sB + b_base[np] + (((ks * 2 + b_kh) ^ b_xm[np]) << 4));
#pragma unroll
            for (int mt = 0; mt < 4; mt++)
#pragma unroll
                for (int nt = 0; nt < 4; nt++)
                    mma_bf16(acc[mt][nt], af[mt],
                             bfr[nt >> 1][(nt & 1) * 2], bfr[nt >> 1][(nt & 1) * 2 + 1]);
        }

        const int li = it + GSTAGES - 1;
        if (li < kniter)
            g_load_stage(sAb + ls * TILE_B, sBb + ls * TILE_B, A, B, bm, bn,
                         kc0 + li * GBK, tid);
        CP_COMMIT();
        cs = (cs + 1 == GSTAGES) ? 0 : cs + 1;
        ls = (ls + 1 == GSTAGES) ? 0 : ls + 1;
    }

    const int tq = lane >> 2, tr4 = lane & 3;
#pragma unroll
    for (int mt = 0; mt < 4; mt++) {
#pragma unroll
        for (int nt = 0; nt < 4; nt++) {
            const int row = bm + wm + mt * 16 + tq;
            const int col = bn + wn + nt * 8 + tr4 * 2;
            float b0 = 0.f, b1 = 0.f;
            if (bias) { b0 = bias[col]; b1 = bias[col + 1]; }
            float2 v0 = {acc[mt][nt][0] + b0, acc[mt][nt][1] + b1};
            float2 v1 = {acc[mt][nt][2] + b0, acc[mt][nt][3] + b1};
            *(float2*)&C[(size_t)row * Nn + col]       = v0;
            *(float2*)&C[(size_t)(row + 8) * Nn + col] = v1;
        }
    }
}

// ---------------- split-K reduction: out = C0 + C1 + bias -------------------
__global__ __launch_bounds__(256)
void reduce2_kernel(const float* __restrict__ C0, const float* __restrict__ C1,
                    const float* __restrict__ bias, float* __restrict__ out)
{
    int i = (blockIdx.x * 256 + threadIdx.x) * 4;
    float4 a = *(const float4*)&C0[i];
    float4 b = *(const float4*)&C1[i];
    const float4 bb = *(const float4*)&bias[i & 2047];
    float4 r = {a.x + b.x + bb.x, a.y + b.y + bb.y,
                a.z + b.z + bb.z, a.w + b.w + bb.w};
    *(float4*)&out[i] = r;
}

// ---------------- fused RMSNorm+RoPE+split for q AND k ----------------------
__global__ __launch_bounds__(256)
void rms2_rope_split_kernel(const float* __restrict__ qkv,
                            const float* __restrict__ wq, const float* __restrict__ wk,
                            const float* __restrict__ cosb, const float* __restrict__ sinb,
                            __nv_bfloat16* __restrict__ qs, __nv_bfloat16* __restrict__ ks,
                            float qscale)
{
    const int row = blockIdx.x;
    const float* pq = qkv + (size_t)row * (3 * DIM);
    const float* pk = pq + DIM;
    const int tid = threadIdx.x;

    float ssq = 0.f, ssk = 0.f;
    for (int i = tid; i < DIM; i += 256) {
        float a = pq[i]; ssq += a * a;
        float b = pk[i]; ssk += b * b;
    }
#pragma unroll
    for (int off = 16; off > 0; off >>= 1) {
        ssq += __shfl_xor_sync(0xffffffffu, ssq, off);
        ssk += __shfl_xor_sync(0xffffffffu, ssk, off);
    }
    __shared__ float redq[8], redk[8];
    __shared__ float scq_s, sck_s;
    if ((tid & 31) == 0) { redq[tid >> 5] = ssq; redk[tid >> 5] = ssk; }
    __syncthreads();
    if (tid == 0) {
        float tq = 0.f, tk = 0.f;
#pragma unroll
        for (int i = 0; i < 8; i++) { tq += redq[i]; tk += redk[i]; }
        scq_s = rsqrtf(tq / (float)DIM + 1e-6f);
        sck_s = rsqrtf(tk / (float)DIM + 1e-6f);
    }
    __syncthreads();
    const float scq = scq_s, sck = sck_s;

    const float* crow = cosb + (size_t)row * HD;
    const float* srow = sinb + (size_t)row * HD;
    for (int pi = tid; pi < DIM / 2; pi += 256) {
        int i0 = 2 * pi;
        int h = i0 >> 7;
        int d = i0 & (HD - 1);
        float c = crow[d], s = srow[d];
        {
            float2 xv = *(const float2*)&pq[i0];
            float e = xv.x * scq * wq[i0];
            float o = xv.y * scq * wq[i0 + 1];
            float rx = (e * c - o * s) * qscale;
            float ry = (o * c + e * s) * qscale;
            uint32_t hi, lo;
            split2(rx, ry, hi, lo);
            __nv_bfloat16* base = qs + (size_t)h * S_LEN * 256 + (size_t)row * 256;
            *(uint32_t*)&base[d]       = hi;
            *(uint32_t*)&base[128 + d] = lo;
        }
        {
            float2 xv = *(const float2*)&pk[i0];
            float e = xv.x * sck * wk[i0];
            float o = xv.y * sck * wk[i0 + 1];
            float rx = e * c - o * s;
            float ry = o * c + e * s;
            uint32_t hi, lo;
            split2(rx, ry, hi, lo);
            __nv_bfloat16* base = ks + (size_t)h * S_LEN * 256 + (size_t)row * 256;
            *(uint32_t*)&base[d]       = hi;
            *(uint32_t*)&base[128 + d] = lo;
        }
    }
}

// ---------------- V transpose + split -> [NH][256][S], 4B stores ------------
__global__ __launch_bounds__(256)
void vsplit_t_kernel(const float* __restrict__ qkv, __nv_bfloat16* __restrict__ vt)
{
    __shared__ float tile[32][33];
    const int s0 = blockIdx.x * 32;
    const int c0 = blockIdx.y * 32;
    const int tx = threadIdx.x & 31;
    const int ty = threadIdx.x >> 5;

#pragma unroll
    for (int i = 0; i < 4; i++) {
        int r = ty + i * 8;
        tile[r][tx] = qkv[(size_t)(s0 + r) * (3 * DIM) + 2 * DIM + c0 + tx];
    }
    __syncthreads();
    const int sx = (threadIdx.x & 15) * 2;
    const int dr0 = threadIdx.x >> 4;
#pragma unroll
    for (int i = 0; i < 2; i++) {
        int dr = dr0 + i * 16;
        int dg = c0 + dr;
        int h = dg >> 7, d = dg & 127;
        float v0 = tile[sx][dr];
        float v1 = tile[sx + 1][dr];
        uint32_t hi, lo;
        split2(v0, v1, hi, lo);
        size_t base = (size_t)h * 256 * S_LEN;
        *(uint32_t*)&vt[base + (size_t)d * S_LEN + s0 + sx]         = hi;
        *(uint32_t*)&vt[base + (size_t)(d + 128) * S_LEN + s0 + sx] = lo;
    }
}

// ---------------- tensor-core flash attention (R11: chunked softmax/PV) -----
#define K_SM_BYTES  (64 * 512)
#define V_SM_BYTES  (256 * 128)
#define KV_ST       (K_SM_BYTES + V_SM_BYTES)
#define ATTN_SMEM   (3 * KV_ST)

__device__ __forceinline__ void attn_load_kv(uint32_t kvb,
    const __nv_bfloat16* __restrict__ ksrc0, const __nv_bfloat16* __restrict__ vsrc0,
    int kt, int tid)
{
    const __nv_bfloat16* ksrc = ksrc0 + (size_t)kt * 64 * 256;
#pragma unroll
    for (int u = 0; u < 8; u++) {
        int c = tid + u * 256;
        int r = c >> 5, ch = c & 31;
        cp_async16(kvb + r * 512 + ((ch ^ (r & 7)) << 4), ksrc + (size_t)r * 256 + ch * 8);
    }
    const __nv_bfloat16* vsrc = vsrc0 + kt * 64;
    const uint32_t vb = kvb + K_SM_BYTES;
#pragma unroll
    for (int u = 0; u < 8; u++) {
        int c = tid + u * 256;
        int r = c >> 3, ch = c & 7;
        cp_async16(vb + r * 128 + ((ch ^ (r & 7)) << 4), vsrc + (size_t)r * S_LEN + ch * 8);
    }
}

__global__ __launch_bounds__(256, 1)
void attn_mma_kernel(const __nv_bfloat16* __restrict__ qs,
                     const __nv_bfloat16* __restrict__ ks,
                     const __nv_bfloat16* __restrict__ vt,
                     __nv_bfloat16* __restrict__ ao3, const int* __restrict__ seq_lens)
{
    extern __shared__ __align__(1024) char smem[];
    const uint32_t sb = smem_u32(smem);
    const int tid = threadIdx.x, lane = tid & 31, wid = tid >> 5;
    const int qb = blockIdx.x, h = blockIdx.y;

    const int seqlen = seq_lens[0];
    const int ntiles = (seqlen + 63) >> 6;

    const __nv_bfloat16* qsrc  = qs + ((size_t)h * S_LEN + qb * 128) * 256;
    const __nv_bfloat16* ksrc0 = ks + (size_t)h * S_LEN * 256;
    const __nv_bfloat16* vsrc0 = vt + (size_t)h * 256 * S_LEN;

    const uint32_t qtmp = sb + 2 * KV_ST;
#pragma unroll
    for (int u = 0; u < 16; u++) {
        int c = tid + u * 256;
        int r = c >> 5, ch = c & 31;
        cp_async16(qtmp + r * 512 + ((ch ^ (r & 7)) << 4), qsrc + (size_t)r * 256 + ch * 8);
    }
    CP_COMMIT();
    attn_load_kv(sb, ksrc0, vsrc0, 0, tid);
    CP_COMMIT();
    CP_WAIT1();
    __syncthreads();

    const int a_row = wid * 16 + (lane & 15);
    const uint32_t a_off = a_row * 512;
    const int a_x = a_row & 7;
    const int a_k16 = lane >> 4;
    uint32_t qh[8][4], ql[8][4];
#pragma unroll
    for (int kst = 0; kst < 8; kst++) {
        ldmx4(qh[kst][0], qh[kst][1], qh[kst][2], qh[kst][3],
              qtmp + a_off + (((kst * 2 + a_k16) ^ a_x) << 4));
        ldmx4(ql[kst][0], ql[kst][1], ql[kst][2], ql[kst][3],
              qtmp + a_off + (((16 + kst * 2 + a_k16) ^ a_x) << 4));
    }
    __syncthreads();

    if (ntiles > 1) {
        attn_load_kv(sb + KV_ST, ksrc0, vsrc0, 1, tid);
        CP_COMMIT();
    }

    const int b_row = (lane & 7) + ((lane >> 4) << 3);
    const int b_k16 = (lane >> 3) & 1;

    uint32_t kb_off[4]; int kb_x[4];
#pragma unroll
    for (int np = 0; np < 4; np++) {
        int row = np * 16 + b_row;
        kb_off[np] = row * 512; kb_x[np] = row & 7;
    }
    uint32_t vb_off[8]; int vb_x[8];
#pragma unroll
    for (int np = 0; np < 8; np++) {
        int row = np * 16 + b_row;
        vb_off[np] = row * 128; vb_x[np] = row & 7;
    }

    float o[16][4];
#pragma unroll
    for (int nt = 0; nt < 16; nt++)
#pragma unroll
        for (int c = 0; c < 4; c++) o[nt][c] = 0.f;
    float mA = -1e30f, mB = -1e30f, lA = 0.f, lB = 0.f;

    int stg = 0;
    for (int kt = 0; kt < ntiles; kt++) {
        if (kt + 2 < ntiles) {
            int ps = stg + 2; if (ps >= 3) ps -= 3;
            attn_load_kv(sb + ps * KV_ST, ksrc0, vsrc0, kt + 2, tid);
            CP_COMMIT();
        }
        const int na = ntiles - 1 - kt;
        if (na >= 2)      { CP_WAIT2(); }
        else if (na == 1) { CP_WAIT1(); }
        else              { CP_WAIT0(); }
        __syncthreads();
        const uint32_t ksm = sb + stg * KV_ST;
        const uint32_t vsm = ksm + K_SM_BYTES;

        float s[8][4];
#pragma unroll
        for (int nt = 0; nt < 8; nt++)
#pragma unroll
            for (int c = 0; c < 4; c++) s[nt][c] = 0.f;

#pragma unroll
        for (int kst = 0; kst < 8; kst++) {
#pragma unroll
            for (int np = 0; np < 4; np++) {
                uint32_t bh[4], bl[4];
                ldmx4(bh[0], bh[1], bh[2], bh[3],
                      ksm + kb_off[np] + (((kst * 2 + b_k16) ^ kb_x[np]) << 4));
                ldmx4(bl[0], bl[1], bl[2], bl[3],
                      ksm + kb_off[np] + (((16 + kst * 2 + b_k16) ^ kb_x[np]) << 4));
                mma_bf16(s[2*np],   qh[kst], bh[0], bh[1]);
                mma_bf16(s[2*np+1], qh[kst], bh[2], bh[3]);
                mma_bf16(s[2*np],   qh[kst], bl[0], bl[1]);
                mma_bf16(s[2*np+1], qh[kst], bl[2], bl[3]);
                mma_bf16(s[2*np],   ql[kst], bh[0], bh[1]);
                mma_bf16(s[2*np+1], ql[kst], bh[2], bh[3]);
            }
        }

        if (kt * 64 + 64 > seqlen) {
            const int kbase = kt * 64 + (lane & 3) * 2;
#pragma unroll
            for (int nt = 0; nt < 8; nt++)
#pragma unroll
                for (int c = 0; c < 4; c++) {
                    int gk = kbase + nt * 8 + (c & 1);
                    if (gk >= seqlen) s[nt][c] = -1e30f;
                }
        }

        float pmA = -1e30f, pmB = -1e30f;
#pragma unroll
        for (int nt = 0; nt < 8; nt++) {
            pmA = fmaxf(pmA, fmaxf(s[nt][0], s[nt][1]));
            pmB = fmaxf(pmB, fmaxf(s[nt][2], s[nt][3]));
        }
        pmA = fmaxf(pmA, __shfl_xor_sync(0xffffffffu, pmA, 1));
        pmA = fmaxf(pmA, __shfl_xor_sync(0xffffffffu, pmA, 2));
        pmB = fmaxf(pmB, __shfl_xor_sync(0xffffffffu, pmB, 1));
        pmB = fmaxf(pmB, __shfl_xor_sync(0xffffffffu, pmB, 2));

        const float mnA = fmaxf(mA, pmA), mnB = fmaxf(mB, pmB);
        const float fA = __expf(mA - mnA), fB = __expf(mB - mnB);
        float sumA = 0.f, sumB = 0.f;

#pragma unroll
        for (int kk = 0; kk < 4; kk++) {
            const int n0 = 2 * kk, n1 = 2 * kk + 1;
            s[n0][0] = __expf(s[n0][0] - mnA); sumA += s[n0][0];
            s[n0][1] = __expf(s[n0][1] - mnA); sumA += s[n0][1];
            s[n0][2] = __expf(s[n0][2] - mnB); sumB += s[n0][2];
            s[n0][3] = __expf(s[n0][3] - mnB); sumB += s[n0][3];
            s[n1][0] = __expf(s[n1][0] - mnA); sumA += s[n1][0];
            s[n1][1] = __expf(s[n1][1] - mnA); sumA += s[n1][1];
            s[n1][2] = __expf(s[n1][2] - mnB); sumB += s[n1][2];
            s[n1][3] = __expf(s[n1][3] - mnB); sumB += s[n1][3];

            uint32_t ph[4], pl[4];
            split2(s[n0][0], s[n0][1], ph[0], pl[0]);
            split2(s[n0][2], s[n0][3], ph[1], pl[1]);
            split2(s[n1][0], s[n1][1], ph[2], pl[2]);
            split2(s[n1][2], s[n1][3], ph[3], pl[3]);

#pragma unroll
            for (int np = 0; np < 8; np++) {
                if (kk == 0) {
                    o[2*np][0]   *= fA; o[2*np][1]   *= fA;
                    o[2*np][2]   *= fB; o[2*np][3]   *= fB;
                    o[2*np+1][0] *= fA; o[2*np+1][1] *= fA;
                    o[2*np+1][2] *= fB; o[2*np+1][3] *= fB;
                }
                uint32_t bvh[4], bvl[4];
                ldmx4(bvh[0], bvh[1], bvh[2], bvh[3],
                      vsm + vb_off[np] + (((kk * 2 + b_k16) ^ vb_x[np]) << 4));
                ldmx4(bvl[0], bvl[1], bvl[2], bvl[3],
                      vsm + 128 * 128 + vb_off[np] + (((kk * 2 + b_k16) ^ vb_x[np]) << 4));
                mma_bf16(o[2*np],   ph, bvh[0], bvh[1]);
                mma_bf16(o[2*np+1], ph, bvh[2], bvh[3]);
                mma_bf16(o[2*np],   ph, bvl[0], bvl[1]);
                mma_bf16(o[2*np+1], ph, bvl[2], bvl[3]);
                mma_bf16(o[2*np],   pl, bvh[0], bvh[1]);
                mma_bf16(o[2*np+1], pl, bvh[2], bvh[3]);
            }
        }

        sumA += __shfl_xor_sync(0xffffffffu, sumA, 1);
        sumA += __shfl_xor_sync(0xffffffffu, sumA, 2);
        sumB += __shfl_xor_sync(0xffffffffu, sumB, 1);
        sumB += __shfl_xor_sync(0xffffffffu, sumB, 2);
        mA = mnA; mB = mnB;
        lA = lA * fA + sumA;
        lB = lB * fB + sumB;

        __syncthreads();
        stg = (stg + 1 == 3) ? 0 : stg + 1;
    }

    const float iA = 1.f / lA, iB = 1.f / lB;
    const int row0 = qb * 128 + wid * 16 + (lane >> 2);
    const int col0 = h * 128 + (lane & 3) * 2;
#pragma unroll
    for (int nt = 0; nt < 16; nt++) {
        float xA = o[nt][0] * iA, yA = o[nt][1] * iA;
        float xB = o[nt][2] * iB, yB = o[nt][3] * iB;
        uint32_t hA, loA, hB, loB;
        split2(xA, yA, hA, loA);
        split2(xB, yB, hB, loB);
        __nv_bfloat16* pA = ao3 + (size_t)row0 * K3 + col0 + nt * 8;
        __nv_bfloat16* pB = ao3 + (size_t)(row0 + 8) * K3 + col0 + nt * 8;
        *(uint32_t*)&pA[0]        = hA;
        *(uint32_t*)&pA[DIM]      = hA;
        *(uint32_t*)&pA[2 * DIM]  = loA;
        *(uint32_t*)&pB[0]        = hB;
        *(uint32_t*)&pB[DIM]      = hB;
        *(uint32_t*)&pB[2 * DIM]  = loB;
    }
}

// ---------------- launch ----------------------------------------------------
extern "C" void kernel_launch(void* const* d_in, const int* in_sizes, int n_in,
                              void* d_out, int out_size)
{
    const float* x    = (const float*)d_in[0];
    const float* Wq   = (const float*)d_in[1];
    const float* bq   = (const float*)d_in[2];
    const float* Wk   = (const float*)d_in[3];
    const float* bk   = (const float*)d_in[4];
    const float* Wv   = (const float*)d_in[5];
    const float* bv   = (const float*)d_in[6];
    const float* Wo   = (const float*)d_in[7];
    const float* bo   = (const float*)d_in[8];
    const float* nqw  = (const float*)d_in[9];
    const float* nkw  = (const float*)d_in[10];
    const float* cosb = (const float*)d_in[11];
    const float* sinb = (const float*)d_in[12];
    const int*   seql = (const int*)d_in[13];
    float* out = (float*)d_out;

    float *qkv, *bias3;
    __nv_bfloat16 *x3, *ao3, *w3, *qsb, *ksb, *vtb;
    cudaGetSymbolAddress((void**)&qkv,   g_qkv);
    cudaGetSymbolAddress((void**)&bias3, g_bias3);
    cudaGetSymbolAddress((void**)&x3,    g_x3);
    cudaGetSymbolAddress((void**)&ao3,   g_ao3);
    cudaGetSymbolAddress((void**)&w3,    g_w3);
    cudaGetSymbolAddress((void**)&qsb,   g_qs);
    cudaGetSymbolAddress((void**)&ksb,   g_ks);
    cudaGetSymbolAddress((void**)&vtb,   g_vt);

    cudaFuncSetAttribute(gemm_mma_kernel, cudaFuncAttributeMaxDynamicSharedMemorySize, SMEM_G);
    cudaFuncSetAttribute(attn_mma_kernel, cudaFuncAttributeMaxDynamicSharedMemorySize, ATTN_SMEM);

    cvt_all_kernel<<<CVT_BLOCKS, 256>>>(x, Wq, Wk, Wv, Wo, x3, w3);
    bias3_kernel<<<(3 * DIM + 255) / 256, 256>>>(bq, bk, bv, bias3);

    // fused QKV projection (full-K, bias, single z-slice)
    gemm_mma_kernel<<<dim3(3 * DIM / GBN, S_LEN / GBM, 1), 256, SMEM_G>>>(
        x3, w3, bias3, qkv, 3 * DIM, K3 / GBK, 0);

    const float qscale = 0.08838834764831845f;   // 1/sqrt(128)
    rms2_rope_split_kernel<<<S_LEN, 256>>>(qkv, nqw, nkw, cosb, sinb, qsb, ksb, qscale);
    vsplit_t_kernel<<<dim3(S_LEN / 32, DIM / 32), 256>>>(qkv, vtb);

    attn_mma_kernel<<<dim3(S_LEN / 128, NH), 256, ATTN_SMEM>>>(qsb, ksb, vtb, ao3, seql);

    // output projection: split-K2 in ONE launch (grid.z = 2 co-schedules halves)
    float* C0 = qkv;
    const __nv_bfloat16* Bo = w3 + 3 * (size_t)DIM * K3;
    gemm_mma_kernel<<<dim3(DIM / GBN, S_LEN / GBM, 2), 256, SMEM_G>>>(
        ao3, Bo, nullptr, C0, DIM, K3 / (2 * GBK), (size_t)S_LEN * DIM);
    reduce2_kernel<<<S_LEN * DIM / 4 / 256, 256>>>(C0, C0 + (size_t)S_LEN * DIM, bo, out);
}

// round 15
// speedup vs baseline: 1.0684x; 1.0103x over previous
#include <cuda_runtime.h>
#include <cuda_bf16.h>
#include <math.h>
#include <stdint.h>

#define S_LEN 3072
#define DIM   2048
#define NH    16
#define HD    128
#define K3    (3*DIM)   // 6144: [hi | hi | lo] x [hi | lo | hi]

// ---------------- scratch (device globals; no allocations allowed) ----------
__device__ __align__(16) float g_qkv[S_LEN * 3 * DIM];
__device__ __align__(16) float g_bias3[3 * DIM];
__device__ __align__(16) __nv_bfloat16 g_x3 [S_LEN * K3];
__device__ __align__(16) __nv_bfloat16 g_ao3[S_LEN * K3];
__device__ __align__(16) __nv_bfloat16 g_w3 [4][DIM * K3];
__device__ __align__(16) __nv_bfloat16 g_qs [NH * S_LEN * 256]; // [h][s][hi128|lo128]
__device__ __align__(16) __nv_bfloat16 g_ks [NH * S_LEN * 256];
__device__ __align__(16) __nv_bfloat16 g_vt [NH * 256 * S_LEN]; // [h][d:hi,d+128:lo][s]

// ---------------- PTX helpers ----------------------------------------------
__device__ __forceinline__ uint32_t smem_u32(const void* p) {
    uint32_t a;
    asm("{ .reg .u64 t; cvta.to.shared.u64 t, %1; cvt.u32.u64 %0, t; }" : "=r"(a) : "l"(p));
    return a;
}
__device__ __forceinline__ void cp_async16(uint32_t saddr, const void* g) {
    asm volatile("cp.async.cg.shared.global [%0], [%1], 16;" :: "r"(saddr), "l"(g));
}
#define CP_COMMIT() asm volatile("cp.async.commit_group;" ::: "memory")
#define CP_WAIT2()  asm volatile("cp.async.wait_group 2;" ::: "memory")
#define CP_WAIT1()  asm volatile("cp.async.wait_group 1;" ::: "memory")
#define CP_WAIT0()  asm volatile("cp.async.wait_group 0;" ::: "memory")

__device__ __forceinline__ void ldmx4(uint32_t& r0, uint32_t& r1, uint32_t& r2, uint32_t& r3,
                                      uint32_t addr) {
    asm volatile("ldmatrix.sync.aligned.m8n8.x4.shared.b16 {%0,%1,%2,%3}, [%4];"
                 : "=r"(r0), "=r"(r1), "=r"(r2), "=r"(r3) : "r"(addr));
}
__device__ __forceinline__ void mma_bf16(float* c, const uint32_t* a, uint32_t b0, uint32_t b1) {
    asm volatile("mma.sync.aligned.m16n8k16.row.col.f32.bf16.bf16.f32 "
                 "{%0,%1,%2,%3}, {%4,%5,%6,%7}, {%8,%9}, {%0,%1,%2,%3};"
                 : "+f"(c[0]), "+f"(c[1]), "+f"(c[2]), "+f"(c[3])
                 : "r"(a[0]), "r"(a[1]), "r"(a[2]), "r"(a[3]), "r"(b0), "r"(b1));
}
__device__ __forceinline__ void split2(float a, float b, uint32_t& hi, uint32_t& lo) {
    __nv_bfloat16 ha = __float2bfloat16(a), hb = __float2bfloat16(b);
    __nv_bfloat16 la = __float2bfloat16(a - __bfloat162float(ha));
    __nv_bfloat16 lb = __float2bfloat16(b - __bfloat162float(hb));
    __nv_bfloat162 H; H.x = ha; H.y = hb;
    __nv_bfloat162 L; L.x = la; L.y = lb;
    hi = *reinterpret_cast<uint32_t*>(&H);
    lo = *reinterpret_cast<uint32_t*>(&L);
}

// ---------------- fused split-bf16 conversion + bias concat -----------------
#define NXQ (S_LEN * DIM / 4)
#define NWQ (DIM * DIM / 4)
#define CVT_MAIN ((NXQ + 4 * NWQ) / 256)       // 22528
#define CVT_BLOCKS (CVT_MAIN + 24)             // +24 blocks: bias3 concat (6144 elems)

__global__ __launch_bounds__(256)
void cvt_all_kernel(const float* __restrict__ x,
                    const float* __restrict__ Wq, const float* __restrict__ Wk,
                    const float* __restrict__ Wv, const float* __restrict__ Wo,
                    const float* __restrict__ bq, const float* __restrict__ bk,
                    const float* __restrict__ bv,
                    __nv_bfloat16* __restrict__ x3, __nv_bfloat16* __restrict__ w3,
                    float* __restrict__ bias3)
{
    if (blockIdx.x >= CVT_MAIN) {
        int i = (blockIdx.x - CVT_MAIN) * 256 + threadIdx.x;
        bias3[i] = (i < DIM) ? bq[i] : (i < 2 * DIM ? bk[i - DIM] : bv[i - 2 * DIM]);
        return;
    }
    int p = blockIdx.x * 256 + threadIdx.x;
    const float* src;
    __nv_bfloat16* dst;
    int mode, lp;
    if (p < NXQ) {
        src = x; dst = x3; mode = 0; lp = p;
    } else {
        int q = (p - NXQ) >> 20;
        lp = (p - NXQ) & (NWQ - 1);
        src = (q == 0) ? Wq : (q == 1) ? Wk : (q == 2) ? Wv : Wo;
        dst = w3 + (size_t)q * DIM * K3;
        mode = 1;
    }
    int i = lp * 4;
    float4 v = *(const float4*)&src[i];
    uint32_t hi0, lo0, hi1, lo1;
    split2(v.x, v.y, hi0, lo0);
    split2(v.z, v.w, hi1, lo1);
    uint2 hip = {hi0, hi1};
    uint2 lop = {lo0, lo1};
    int row = i >> 11;
    int c   = i & 2047;
    __nv_bfloat16* base = dst + (size_t)row * K3 + c;
    if (mode == 0) {
        *(uint2*)&base[0]       = hip;
        *(uint2*)&base[DIM]     = hip;
        *(uint2*)&base[2 * DIM] = lop;
    } else {
        *(uint2*)&base[0]       = hip;
        *(uint2*)&base[DIM]     = lop;
        *(uint2*)&base[2 * DIM] = hip;
    }
}

// ---------------- mma.sync GEMM: CTA 128x128, 3-stage cp.async, 2 CTA/SM ----
#define GBM 128
#define GBN 128
#define GBK 64
#define GSTAGES 3
#define GNITER (K3 / GBK)
#define TILE_B 16384
#define SMEM_G (GSTAGES * TILE_B * 2)   // 98304

__device__ __forceinline__ void g_load_stage(uint32_t sA, uint32_t sB,
    const __nv_bfloat16* __restrict__ A, const __nv_bfloat16* __restrict__ B,
    int bm, int bn, int kc, int tid)
{
#pragma unroll
    for (int i = 0; i < 4; i++) {
        int c = tid + i * 256;
        int row = c >> 3, cc = c & 7;
        cp_async16(sA + row * 128 + ((cc ^ (row & 7)) << 4),
                   A + (size_t)(bm + row) * K3 + kc + cc * 8);
    }
#pragma unroll
    for (int i = 0; i < 4; i++) {
        int c = tid + i * 256;
        int row = c >> 3, cc = c & 7;
        cp_async16(sB + row * 128 + ((cc ^ (row & 7)) << 4),
                   B + (size_t)(bn + row) * K3 + kc + cc * 8);
    }
}

__global__ __launch_bounds__(256, 2)
void gemm_mma_kernel(const __nv_bfloat16* __restrict__ A,
                     const __nv_bfloat16* __restrict__ B,
                     const float* __restrict__ bias, float* __restrict__ C, int Nn)
{
    extern __shared__ __align__(1024) char smem[];
    const uint32_t sb = smem_u32(smem);
    const uint32_t sAb = sb;
    const uint32_t sBb = sb + GSTAGES * TILE_B;

    const int tid = threadIdx.x;
    const int wid = tid >> 5, lane = tid & 31;
    const int bm = blockIdx.y * GBM, bn = blockIdx.x * GBN;
    const int wm = (wid & 1) * 64;
    const int wn = (wid >> 1) * 32;

    const int a_row = lane & 15;
    const int a_kh  = (lane >> 4);
    const int b_row = (lane & 7) + ((lane >> 4) << 3);
    const int b_kh  = (lane >> 3) & 1;

    float acc[4][4][4];
#pragma unroll
    for (int mt = 0; mt < 4; mt++)
#pragma unroll
        for (int nt = 0; nt < 4; nt++)
#pragma unroll
            for (int r = 0; r < 4; r++) acc[mt][nt][r] = 0.f;

#pragma unroll
    for (int s = 0; s < GSTAGES - 1; s++) {
        g_load_stage(sAb + s * TILE_B, sBb + s * TILE_B, A, B, bm, bn, s * GBK, tid);
        CP_COMMIT();
    }

    uint32_t a_base[4], b_base[2]; int a_xm[4], b_xm[2];
#pragma unroll
    for (int mt = 0; mt < 4; mt++) {
        int row = wm + mt * 16 + a_row;
        a_base[mt] = row * 128;
        a_xm[mt] = row & 7;
    }
#pragma unroll
    for (int np = 0; np < 2; np++) {
        int row = wn + np * 16 + b_row;
        b_base[np] = row * 128;
        b_xm[np] = row & 7;
    }

    int cs = 0, ls = GSTAGES - 1;
    for (int it = 0; it < GNITER; it++) {
        CP_WAIT1();
        __syncthreads();
        const uint32_t sA = sAb + cs * TILE_B;
        const uint32_t sB = sBb + cs * TILE_B;

#pragma unroll
        for (int ks = 0; ks < 4; ks++) {
            uint32_t af[4][4];
#pragma unroll
            for (int mt = 0; mt < 4; mt++)
                ldmx4(af[mt][0], af[mt][1], af[mt][2], af[mt][3],
                      sA + a_base[mt] + (((ks * 2 + a_kh) ^ a_xm[mt]) << 4));
            uint32_t bfr[2][4];
#pragma unroll
            for (int np = 0; np < 2; np++)
                ldmx4(bfr[np][0], bfr[np][1], bfr[np][2], bfr[np][3],
                      sB + b_base[np] + (((ks * 2 + b_kh) ^ b_xm[np]) << 4));
#pragma unroll
            for (int mt = 0; mt < 4; mt++)
#pragma unroll
                for (int nt = 0; nt < 4; nt++)
                    mma_bf16(acc[mt][nt], af[mt],
                             bfr[nt >> 1][(nt & 1) * 2], bfr[nt >> 1][(nt & 1) * 2 + 1]);
        }

        const int li = it + GSTAGES - 1;
        if (li < GNITER)
            g_load_stage(sAb + ls * TILE_B, sBb + ls * TILE_B, A, B, bm, bn, li * GBK, tid);
        CP_COMMIT();
        cs = (cs + 1 == GSTAGES) ? 0 : cs + 1;
        ls = (ls + 1 == GSTAGES) ? 0 : ls + 1;
    }

    const int tq = lane >> 2, tr4 = lane & 3;
#pragma unroll
    for (int mt = 0; mt < 4; mt++) {
#pragma unroll
        for (int nt = 0; nt < 4; nt++) {
            const int row = bm + wm + mt * 16 + tq;
            const int col = bn + wn + nt * 8 + tr4 * 2;
            const float b0 = bias[col], b1 = bias[col + 1];
            float2 v0 = {acc[mt][nt][0] + b0, acc[mt][nt][1] + b1};
            float2 v1 = {acc[mt][nt][2] + b0, acc[mt][nt][3] + b1};
            *(float2*)&C[(size_t)row * Nn + col]       = v0;
            *(float2*)&C[(size_t)(row + 8) * Nn + col] = v1;
        }
    }
}

// ---------------- fused RMSNorm+RoPE+split, single global read (smem cache) -
__global__ __launch_bounds__(256)
void rms2_rope_split_kernel(const float* __restrict__ qkv,
                            const float* __restrict__ wq, const float* __restrict__ wk,
                            const float* __restrict__ cosb, const float* __restrict__ sinb,
                            __nv_bfloat16* __restrict__ qs, __nv_bfloat16* __restrict__ ks,
                            float qscale)
{
    __shared__ float rowq[DIM], rowk[DIM];   // 16 KB
    const int row = blockIdx.x;
    const float* pq = qkv + (size_t)row * (3 * DIM);
    const float* pk = pq + DIM;
    const int tid = threadIdx.x;

    float ssq = 0.f, ssk = 0.f;
#pragma unroll
    for (int u = 0; u < 2; u++) {
        int i = (tid + u * 256) * 4;
        float4 a = *(const float4*)&pq[i];
        float4 b = *(const float4*)&pk[i];
        ssq += a.x * a.x + a.y * a.y + a.z * a.z + a.w * a.w;
        ssk += b.x * b.x + b.y * b.y + b.z * b.z + b.w * b.w;
        *(float4*)&rowq[i] = a;
        *(float4*)&rowk[i] = b;
    }
#pragma unroll
    for (int off = 16; off > 0; off >>= 1) {
        ssq += __shfl_xor_sync(0xffffffffu, ssq, off);
        ssk += __shfl_xor_sync(0xffffffffu, ssk, off);
    }
    __shared__ float redq[8], redk[8];
    __shared__ float scq_s, sck_s;
    if ((tid & 31) == 0) { redq[tid >> 5] = ssq; redk[tid >> 5] = ssk; }
    __syncthreads();
    if (tid == 0) {
        float tq = 0.f, tk = 0.f;
#pragma unroll
        for (int i = 0; i < 8; i++) { tq += redq[i]; tk += redk[i]; }
        scq_s = rsqrtf(tq / (float)DIM + 1e-6f);
        sck_s = rsqrtf(tk / (float)DIM + 1e-6f);
    }
    __syncthreads();
    const float scq = scq_s, sck = sck_s;

    const float* crow = cosb + (size_t)row * HD;
    const float* srow = sinb + (size_t)row * HD;
#pragma unroll
    for (int u = 0; u < 4; u++) {
        int pi = tid + u * 256;
        int i0 = 2 * pi;
        int h = i0 >> 7;
        int d = i0 & (HD - 1);
        float c = crow[d], s = srow[d];
        const size_t hsoff = (size_t)h * S_LEN * 256 + (size_t)row * 256;
        {
            float e = rowq[i0]     * scq * wq[i0];
            float o = rowq[i0 + 1] * scq * wq[i0 + 1];
            float rx = (e * c - o * s) * qscale;
            float ry = (o * c + e * s) * qscale;
            uint32_t hi, lo;
            split2(rx, ry, hi, lo);
            __nv_bfloat16* base = qs + hsoff;
            *(uint32_t*)&base[d]       = hi;
            *(uint32_t*)&base[128 + d] = lo;
        }
        {
            float e = rowk[i0]     * sck * wk[i0];
            float o = rowk[i0 + 1] * sck * wk[i0 + 1];
            float rx = e * c - o * s;
            float ry = o * c + e * s;
            uint32_t hi, lo;
            split2(rx, ry, hi, lo);
            __nv_bfloat16* base = ks + hsoff;
            *(uint32_t*)&base[d]       = hi;
            *(uint32_t*)&base[128 + d] = lo;
        }
    }
}

// ---------------- V transpose + split -> [NH][256][S], 4B stores ------------
__global__ __launch_bounds__(256)
void vsplit_t_kernel(const float* __restrict__ qkv, __nv_bfloat16* __restrict__ vt)
{
    __shared__ float tile[32][33];
    const int s0 = blockIdx.x * 32;
    const int c0 = blockIdx.y * 32;
    const int tx = threadIdx.x & 31;
    const int ty = threadIdx.x >> 5;

#pragma unroll
    for (int i = 0; i < 4; i++) {
        int r = ty + i * 8;
        tile[r][tx] = qkv[(size_t)(s0 + r) * (3 * DIM) + 2 * DIM + c0 + tx];
    }
    __syncthreads();
    const int sx = (threadIdx.x & 15) * 2;
    const int dr0 = threadIdx.x >> 4;
#pragma unroll
    for (int i = 0; i < 2; i++) {
        int dr = dr0 + i * 16;
        int dg = c0 + dr;
        int h = dg >> 7, d = dg & 127;
        float v0 = tile[sx][dr];
        float v1 = tile[sx + 1][dr];
        uint32_t hi, lo;
        split2(v0, v1, hi, lo);
        size_t base = (size_t)h * 256 * S_LEN;
        *(uint32_t*)&vt[base + (size_t)d * S_LEN + s0 + sx]         = hi;
        *(uint32_t*)&vt[base + (size_t)(d + 128) * S_LEN + s0 + sx] = lo;
    }
}

// ---------------- tensor-core flash attention (R11: chunked softmax/PV) -----
#define K_SM_BYTES  (64 * 512)
#define V_SM_BYTES  (256 * 128)
#define KV_ST       (K_SM_BYTES + V_SM_BYTES)
#define ATTN_SMEM   (3 * KV_ST)

__device__ __forceinline__ void attn_load_kv(uint32_t kvb,
    const __nv_bfloat16* __restrict__ ksrc0, const __nv_bfloat16* __restrict__ vsrc0,
    int kt, int tid)
{
    const __nv_bfloat16* ksrc = ksrc0 + (size_t)kt * 64 * 256;
#pragma unroll
    for (int u = 0; u < 8; u++) {
        int c = tid + u * 256;
        int r = c >> 5, ch = c & 31;
        cp_async16(kvb + r * 512 + ((ch ^ (r & 7)) << 4), ksrc + (size_t)r * 256 + ch * 8);
    }
    const __nv_bfloat16* vsrc = vsrc0 + kt * 64;
    const uint32_t vb = kvb + K_SM_BYTES;
#pragma unroll
    for (int u = 0; u < 8; u++) {
        int c = tid + u * 256;
        int r = c >> 3, ch = c & 7;
        cp_async16(vb + r * 128 + ((ch ^ (r & 7)) << 4), vsrc + (size_t)r * S_LEN + ch * 8);
    }
}

__global__ __launch_bounds__(256, 1)
void attn_mma_kernel(const __nv_bfloat16* __restrict__ qs,
                     const __nv_bfloat16* __restrict__ ks,
                     const __nv_bfloat16* __restrict__ vt,
                     __nv_bfloat16* __restrict__ ao3, const int* __restrict__ seq_lens)
{
    extern __shared__ __align__(1024) char smem[];
    const uint32_t sb = smem_u32(smem);
    const int tid = threadIdx.x, lane = tid & 31, wid = tid >> 5;
    const int qb = blockIdx.x, h = blockIdx.y;

    const int seqlen = seq_lens[0];
    const int ntiles = (seqlen + 63) >> 6;

    const __nv_bfloat16* qsrc  = qs + ((size_t)h * S_LEN + qb * 128) * 256;
    const __nv_bfloat16* ksrc0 = ks + (size_t)h * S_LEN * 256;
    const __nv_bfloat16* vsrc0 = vt + (size_t)h * 256 * S_LEN;

    const uint32_t qtmp = sb + 2 * KV_ST;
#pragma unroll
    for (int u = 0; u < 16; u++) {
        int c = tid + u * 256;
        int r = c >> 5, ch = c & 31;
        cp_async16(qtmp + r * 512 + ((ch ^ (r & 7)) << 4), qsrc + (size_t)r * 256 + ch * 8);
    }
    CP_COMMIT();
    attn_load_kv(sb, ksrc0, vsrc0, 0, tid);
    CP_COMMIT();
    CP_WAIT1();
    __syncthreads();

    const int a_row = wid * 16 + (lane & 15);
    const uint32_t a_off = a_row * 512;
    const int a_x = a_row & 7;
    const int a_k16 = lane >> 4;
    uint32_t qh[8][4], ql[8][4];
#pragma unroll
    for (int kst = 0; kst < 8; kst++) {
        ldmx4(qh[kst][0], qh[kst][1], qh[kst][2], qh[kst][3],
              qtmp + a_off + (((kst * 2 + a_k16) ^ a_x) << 4));
        ldmx4(ql[kst][0], ql[kst][1], ql[kst][2], ql[kst][3],
              qtmp + a_off + (((16 + kst * 2 + a_k16) ^ a_x) << 4));
    }
    __syncthreads();

    if (ntiles > 1) {
        attn_load_kv(sb + KV_ST, ksrc0, vsrc0, 1, tid);
        CP_COMMIT();
    }

    const int b_row = (lane & 7) + ((lane >> 4) << 3);
    const int b_k16 = (lane >> 3) & 1;

    uint32_t kb_off[4]; int kb_x[4];
#pragma unroll
    for (int np = 0; np < 4; np++) {
        int row = np * 16 + b_row;
        kb_off[np] = row * 512; kb_x[np] = row & 7;
    }
    uint32_t vb_off[8]; int vb_x[8];
#pragma unroll
    for (int np = 0; np < 8; np++) {
        int row = np * 16 + b_row;
        vb_off[np] = row * 128; vb_x[np] = row & 7;
    }

    float o[16][4];
#pragma unroll
    for (int nt = 0; nt < 16; nt++)
#pragma unroll
        for (int c = 0; c < 4; c++) o[nt][c] = 0.f;
    float mA = -1e30f, mB = -1e30f, lA = 0.f, lB = 0.f;

    int stg = 0;
    for (int kt = 0; kt < ntiles; kt++) {
        if (kt + 2 < ntiles) {
            int ps = stg + 2; if (ps >= 3) ps -= 3;
            attn_load_kv(sb + ps * KV_ST, ksrc0, vsrc0, kt + 2, tid);
            CP_COMMIT();
        }
        const int na = ntiles - 1 - kt;
        if (na >= 2)      { CP_WAIT2(); }
        else if (na == 1) { CP_WAIT1(); }
        else              { CP_WAIT0(); }
        __syncthreads();
        const uint32_t ksm = sb + stg * KV_ST;
        const uint32_t vsm = ksm + K_SM_BYTES;

        float s[8][4];
#pragma unroll
        for (int nt = 0; nt < 8; nt++)
#pragma unroll
            for (int c = 0; c < 4; c++) s[nt][c] = 0.f;

#pragma unroll
        for (int kst = 0; kst < 8; kst++) {
#pragma unroll
            for (int np = 0; np < 4; np++) {
                uint32_t bh[4], bl[4];
                ldmx4(bh[0], bh[1], bh[2], bh[3],
                      ksm + kb_off[np] + (((kst * 2 + b_k16) ^ kb_x[np]) << 4));
                ldmx4(bl[0], bl[1], bl[2], bl[3],
                      ksm + kb_off[np] + (((16 + kst * 2 + b_k16) ^ kb_x[np]) << 4));
                mma_bf16(s[2*np],   qh[kst], bh[0], bh[1]);
                mma_bf16(s[2*np+1], qh[kst], bh[2], bh[3]);
                mma_bf16(s[2*np],   qh[kst], bl[0], bl[1]);
                mma_bf16(s[2*np+1], qh[kst], bl[2], bl[3]);
                mma_bf16(s[2*np],   ql[kst], bh[0], bh[1]);
                mma_bf16(s[2*np+1], ql[kst], bh[2], bh[3]);
            }
        }

        if (kt * 64 + 64 > seqlen) {
            const int kbase = kt * 64 + (lane & 3) * 2;
#pragma unroll
            for (int nt = 0; nt < 8; nt++)
#pragma unroll
                for (int c = 0; c < 4; c++) {
                    int gk = kbase + nt * 8 + (c & 1);
                    if (gk >= seqlen) s[nt][c] = -1e30f;
                }
        }

        float pmA = -1e30f, pmB = -1e30f;
#pragma unroll
        for (int nt = 0; nt < 8; nt++) {
            pmA = fmaxf(pmA, fmaxf(s[nt][0], s[nt][1]));
            pmB = fmaxf(pmB, fmaxf(s[nt][2], s[nt][3]));
        }
        pmA = fmaxf(pmA, __shfl_xor_sync(0xffffffffu, pmA, 1));
        pmA = fmaxf(pmA, __shfl_xor_sync(0xffffffffu, pmA, 2));
        pmB = fmaxf(pmB, __shfl_xor_sync(0xffffffffu, pmB, 1));
        pmB = fmaxf(pmB, __shfl_xor_sync(0xffffffffu, pmB, 2));

        const float mnA = fmaxf(mA, pmA), mnB = fmaxf(mB, pmB);
        const float fA = __expf(mA - mnA), fB = __expf(mB - mnB);
        float sumA = 0.f, sumB = 0.f;

#pragma unroll
        for (int kk = 0; kk < 4; kk++) {
            const int n0 = 2 * kk, n1 = 2 * kk + 1;
            s[n0][0] = __expf(s[n0][0] - mnA); sumA += s[n0][0];
            s[n0][1] = __expf(s[n0][1] - mnA); sumA += s[n0][1];
            s[n0][2] = __expf(s[n0][2] - mnB); sumB += s[n0][2];
            s[n0][3] = __expf(s[n0][3] - mnB); sumB += s[n0][3];
            s[n1][0] = __expf(s[n1][0] - mnA); sumA += s[n1][0];
            s[n1][1] = __expf(s[n1][1] - mnA); sumA += s[n1][1];
            s[n1][2] = __expf(s[n1][2] - mnB); sumB += s[n1][2];
            s[n1][3] = __expf(s[n1][3] - mnB); sumB += s[n1][3];

            uint32_t ph[4], pl[4];
            split2(s[n0][0], s[n0][1], ph[0], pl[0]);
            split2(s[n0][2], s[n0][3], ph[1], pl[1]);
            split2(s[n1][0], s[n1][1], ph[2], pl[2]);
            split2(s[n1][2], s[n1][3], ph[3], pl[3]);

#pragma unroll
            for (int np = 0; np < 8; np++) {
                if (kk == 0) {
                    o[2*np][0]   *= fA; o[2*np][1]   *= fA;
                    o[2*np][2]   *= fB; o[2*np][3]   *= fB;
                    o[2*np+1][0] *= fA; o[2*np+1][1] *= fA;
                    o[2*np+1][2] *= fB; o[2*np+1][3] *= fB;
                }
                uint32_t bvh[4], bvl[4];
                ldmx4(bvh[0], bvh[1], bvh[2], bvh[3],
                      vsm + vb_off[np] + (((kk * 2 + b_k16) ^ vb_x[np]) << 4));
                ldmx4(bvl[0], bvl[1], bvl[2], bvl[3],
                      vsm + 128 * 128 + vb_off[np] + (((kk * 2 + b_k16) ^ vb_x[np]) << 4));
                mma_bf16(o[2*np],   ph, bvh[0], bvh[1]);
                mma_bf16(o[2*np+1], ph, bvh[2], bvh[3]);
                mma_bf16(o[2*np],   ph, bvl[0], bvl[1]);
                mma_bf16(o[2*np+1], ph, bvl[2], bvl[3]);
                mma_bf16(o[2*np],   pl, bvh[0], bvh[1]);
                mma_bf16(o[2*np+1], pl, bvh[2], bvh[3]);
            }
        }

        sumA += __shfl_xor_sync(0xffffffffu, sumA, 1);
        sumA += __shfl_xor_sync(0xffffffffu, sumA, 2);
        sumB += __shfl_xor_sync(0xffffffffu, sumB, 1);
        sumB += __shfl_xor_sync(0xffffffffu, sumB, 2);
        mA = mnA; mB = mnB;
        lA = lA * fA + sumA;
        lB = lB * fB + sumB;

        __syncthreads();
        stg = (stg + 1 == 3) ? 0 : stg + 1;
    }

    const float iA = 1.f / lA, iB = 1.f / lB;
    const int row0 = qb * 128 + wid * 16 + (lane >> 2);
    const int col0 = h * 128 + (lane & 3) * 2;
#pragma unroll
    for (int nt = 0; nt < 16; nt++) {
        float xA = o[nt][0] * iA, yA = o[nt][1] * iA;
        float xB = o[nt][2] * iB, yB = o[nt][3] * iB;
        uint32_t hA, loA, hB, loB;
        split2(xA, yA, hA, loA);
        split2(xB, yB, hB, loB);
        __nv_bfloat16* pA = ao3 + (size_t)row0 * K3 + col0 + nt * 8;
        __nv_bfloat16* pB = ao3 + (size_t)(row0 + 8) * K3 + col0 + nt * 8;
        *(uint32_t*)&pA[0]        = hA;
        *(uint32_t*)&pA[DIM]      = hA;
        *(uint32_t*)&pA[2 * DIM]  = loA;
        *(uint32_t*)&pB[0]        = hB;
        *(uint32_t*)&pB[DIM]      = hB;
        *(uint32_t*)&pB[2 * DIM]  = loB;
    }
}

// ---------------- launch ----------------------------------------------------
extern "C" void kernel_launch(void* const* d_in, const int* in_sizes, int n_in,
                              void* d_out, int out_size)
{
    const float* x    = (const float*)d_in[0];
    const float* Wq   = (const float*)d_in[1];
    const float* bq   = (const float*)d_in[2];
    const float* Wk   = (const float*)d_in[3];
    const float* bk   = (const float*)d_in[4];
    const float* Wv   = (const float*)d_in[5];
    const float* bv   = (const float*)d_in[6];
    const float* Wo   = (const float*)d_in[7];
    const float* bo   = (const float*)d_in[8];
    const float* nqw  = (const float*)d_in[9];
    const float* nkw  = (const float*)d_in[10];
    const float* cosb = (const float*)d_in[11];
    const float* sinb = (const float*)d_in[12];
    const int*   seql = (const int*)d_in[13];
    float* out = (float*)d_out;

    float *qkv, *bias3;
    __nv_bfloat16 *x3, *ao3, *w3, *qsb, *ksb, *vtb;
    cudaGetSymbolAddress((void**)&qkv,   g_qkv);
    cudaGetSymbolAddress((void**)&bias3, g_bias3);
    cudaGetSymbolAddress((void**)&x3,    g_x3);
    cudaGetSymbolAddress((void**)&ao3,   g_ao3);
    cudaGetSymbolAddress((void**)&w3,    g_w3);
    cudaGetSymbolAddress((void**)&qsb,   g_qs);
    cudaGetSymbolAddress((void**)&ksb,   g_ks);
    cudaGetSymbolAddress((void**)&vtb,   g_vt);

    cudaFuncSetAttribute(gemm_mma_kernel, cudaFuncAttributeMaxDynamicSharedMemorySize, SMEM_G);
    cudaFuncSetAttribute(attn_mma_kernel, cudaFuncAttributeMaxDynamicSharedMemorySize, ATTN_SMEM);

    cvt_all_kernel<<<CVT_BLOCKS, 256>>>(x, Wq, Wk, Wv, Wo, bq, bk, bv, x3, w3, bias3);

    // fused QKV projection (full-K, bias)
    gemm_mma_kernel<<<dim3(3 * DIM / GBN, S_LEN / GBM), 256, SMEM_G>>>(
        x3, w3, bias3, qkv, 3 * DIM);

    const float qscale = 0.08838834764831845f;   // 1/sqrt(128)
    rms2_rope_split_kernel<<<S_LEN, 256>>>(qkv, nqw, nkw, cosb, sinb, qsb, ksb, qscale);
    vsplit_t_kernel<<<dim3(S_LEN / 32, DIM / 32), 256>>>(qkv, vtb);

    attn_mma_kernel<<<dim3(S_LEN / 128, NH), 256, ATTN_SMEM>>>(qsb, ksb, vtb, ao3, seql);

    // output projection (full-K, fused bias — split-K reverted, reduce removed)
    gemm_mma_kernel<<<dim3(DIM / GBN, S_LEN / GBM), 256, SMEM_G>>>(
        ao3, w3 + 3 * (size_t)DIM * K3, bo, out, DIM);
}

// round 16
// speedup vs baseline: 1.0815x; 1.0122x over previous
#include <cuda_runtime.h>
#include <cuda_bf16.h>
#include <math.h>
#include <stdint.h>

#define S_LEN 3072
#define DIM   2048
#define NH    16
#define HD    128
#define K3    (3*DIM)   // 6144: [hi | hi | lo] x [hi | lo | hi]

// ---------------- scratch (device globals; no allocations allowed) ----------
__device__ __align__(16) float g_qkv[S_LEN * 3 * DIM];
__device__ __align__(16) float g_bias3[3 * DIM];
__device__ __align__(16) __nv_bfloat16 g_x3 [S_LEN * K3];
__device__ __align__(16) __nv_bfloat16 g_ao3[S_LEN * K3];
__device__ __align__(16) __nv_bfloat16 g_w3 [4][DIM * K3];
__device__ __align__(16) __nv_bfloat16 g_qs [NH * S_LEN * 256]; // [h][s][hi128|lo128]
__device__ __align__(16) __nv_bfloat16 g_ks [NH * S_LEN * 256];
__device__ __align__(16) __nv_bfloat16 g_vt [NH * 256 * S_LEN]; // [h][d:hi,d+128:lo][s]

// ---------------- PTX helpers ----------------------------------------------
__device__ __forceinline__ uint32_t smem_u32(const void* p) {
    uint32_t a;
    asm("{ .reg .u64 t; cvta.to.shared.u64 t, %1; cvt.u32.u64 %0, t; }" : "=r"(a) : "l"(p));
    return a;
}
__device__ __forceinline__ void cp_async16(uint32_t saddr, const void* g) {
    asm volatile("cp.async.cg.shared.global [%0], [%1], 16;" :: "r"(saddr), "l"(g));
}
#define CP_COMMIT() asm volatile("cp.async.commit_group;" ::: "memory")
#define CP_WAIT2()  asm volatile("cp.async.wait_group 2;" ::: "memory")
#define CP_WAIT1()  asm volatile("cp.async.wait_group 1;" ::: "memory")
#define CP_WAIT0()  asm volatile("cp.async.wait_group 0;" ::: "memory")

__device__ __forceinline__ void ldmx4(uint32_t& r0, uint32_t& r1, uint32_t& r2, uint32_t& r3,
                                      uint32_t addr) {
    asm volatile("ldmatrix.sync.aligned.m8n8.x4.shared.b16 {%0,%1,%2,%3}, [%4];"
                 : "=r"(r0), "=r"(r1), "=r"(r2), "=r"(r3) : "r"(addr));
}
__device__ __forceinline__ void mma_bf16(float* c, const uint32_t* a, uint32_t b0, uint32_t b1) {
    asm volatile("mma.sync.aligned.m16n8k16.row.col.f32.bf16.bf16.f32 "
                 "{%0,%1,%2,%3}, {%4,%5,%6,%7}, {%8,%9}, {%0,%1,%2,%3};"
                 : "+f"(c[0]), "+f"(c[1]), "+f"(c[2]), "+f"(c[3])
                 : "r"(a[0]), "r"(a[1]), "r"(a[2]), "r"(a[3]), "r"(b0), "r"(b1));
}
__device__ __forceinline__ void split2(float a, float b, uint32_t& hi, uint32_t& lo) {
    __nv_bfloat16 ha = __float2bfloat16(a), hb = __float2bfloat16(b);
    __nv_bfloat16 la = __float2bfloat16(a - __bfloat162float(ha));
    __nv_bfloat16 lb = __float2bfloat16(b - __bfloat162float(hb));
    __nv_bfloat162 H; H.x = ha; H.y = hb;
    __nv_bfloat162 L; L.x = la; L.y = lb;
    hi = *reinterpret_cast<uint32_t*>(&H);
    lo = *reinterpret_cast<uint32_t*>(&L);
}

// ---------------- fused split-bf16 conversion + bias concat -----------------
#define NXQ (S_LEN * DIM / 4)
#define NWQ (DIM * DIM / 4)
#define CVT_MAIN ((NXQ + 4 * NWQ) / 256)
#define CVT_BLOCKS (CVT_MAIN + 24)

__global__ __launch_bounds__(256)
void cvt_all_kernel(const float* __restrict__ x,
                    const float* __restrict__ Wq, const float* __restrict__ Wk,
                    const float* __restrict__ Wv, const float* __restrict__ Wo,
                    const float* __restrict__ bq, const float* __restrict__ bk,
                    const float* __restrict__ bv,
                    __nv_bfloat16* __restrict__ x3, __nv_bfloat16* __restrict__ w3,
                    float* __restrict__ bias3)
{
    if (blockIdx.x >= CVT_MAIN) {
        int i = (blockIdx.x - CVT_MAIN) * 256 + threadIdx.x;
        bias3[i] = (i < DIM) ? bq[i] : (i < 2 * DIM ? bk[i - DIM] : bv[i - 2 * DIM]);
        return;
    }
    int p = blockIdx.x * 256 + threadIdx.x;
    const float* src;
    __nv_bfloat16* dst;
    int mode, lp;
    if (p < NXQ) {
        src = x; dst = x3; mode = 0; lp = p;
    } else {
        int q = (p - NXQ) >> 20;
        lp = (p - NXQ) & (NWQ - 1);
        src = (q == 0) ? Wq : (q == 1) ? Wk : (q == 2) ? Wv : Wo;
        dst = w3 + (size_t)q * DIM * K3;
        mode = 1;
    }
    int i = lp * 4;
    float4 v = *(const float4*)&src[i];
    uint32_t hi0, lo0, hi1, lo1;
    split2(v.x, v.y, hi0, lo0);
    split2(v.z, v.w, hi1, lo1);
    uint2 hip = {hi0, hi1};
    uint2 lop = {lo0, lo1};
    int row = i >> 11;
    int c   = i & 2047;
    __nv_bfloat16* base = dst + (size_t)row * K3 + c;
    if (mode == 0) {
        *(uint2*)&base[0]       = hip;
        *(uint2*)&base[DIM]     = hip;
        *(uint2*)&base[2 * DIM] = lop;
    } else {
        *(uint2*)&base[0]       = hip;
        *(uint2*)&base[DIM]     = lop;
        *(uint2*)&base[2 * DIM] = hip;
    }
}

// ---------------- mma.sync GEMM: CTA 128x128, 3-stage cp.async, 2 CTA/SM ----
#define GBM 128
#define GBN 128
#define GBK 64
#define GSTAGES 3
#define GNITER (K3 / GBK)
#define TILE_B 16384
#define SMEM_G (GSTAGES * TILE_B * 2)   // 98304

__device__ __forceinline__ void g_load_stage(uint32_t sA, uint32_t sB,
    const __nv_bfloat16* __restrict__ A, const __nv_bfloat16* __restrict__ B,
    int bm, int bn, int kc, int tid)
{
#pragma unroll
    for (int i = 0; i < 4; i++) {
        int c = tid + i * 256;
        int row = c >> 3, cc = c & 7;
        cp_async16(sA + row * 128 + ((cc ^ (row & 7)) << 4),
                   A + (size_t)(bm + row) * K3 + kc + cc * 8);
    }
#pragma unroll
    for (int i = 0; i < 4; i++) {
        int c = tid + i * 256;
        int row = c >> 3, cc = c & 7;
        cp_async16(sB + row * 128 + ((cc ^ (row & 7)) << 4),
                   B + (size_t)(bn + row) * K3 + kc + cc * 8);
    }
}

__global__ __launch_bounds__(256, 2)
void gemm_mma_kernel(const __nv_bfloat16* __restrict__ A,
                     const __nv_bfloat16* __restrict__ B,
                     const float* __restrict__ bias, float* __restrict__ C, int Nn)
{
    extern __shared__ __align__(1024) char smem[];
    const uint32_t sb = smem_u32(smem);
    const uint32_t sAb = sb;
    const uint32_t sBb = sb + GSTAGES * TILE_B;

    const int tid = threadIdx.x;
    const int wid = tid >> 5, lane = tid & 31;
    const int bm = blockIdx.y * GBM, bn = blockIdx.x * GBN;
    const int wm = (wid & 1) * 64;
    const int wn = (wid >> 1) * 32;

    const int a_row = lane & 15;
    const int a_kh  = (lane >> 4);
    const int b_row = (lane & 7) + ((lane >> 4) << 3);
    const int b_kh  = (lane >> 3) & 1;

    float acc[4][4][4];
#pragma unroll
    for (int mt = 0; mt < 4; mt++)
#pragma unroll
        for (int nt = 0; nt < 4; nt++)
#pragma unroll
            for (int r = 0; r < 4; r++) acc[mt][nt][r] = 0.f;

#pragma unroll
    for (int s = 0; s < GSTAGES - 1; s++) {
        g_load_stage(sAb + s * TILE_B, sBb + s * TILE_B, A, B, bm, bn, s * GBK, tid);
        CP_COMMIT();
    }

    uint32_t a_base[4], b_base[2]; int a_xm[4], b_xm[2];
#pragma unroll
    for (int mt = 0; mt < 4; mt++) {
        int row = wm + mt * 16 + a_row;
        a_base[mt] = row * 128;
        a_xm[mt] = row & 7;
    }
#pragma unroll
    for (int np = 0; np < 2; np++) {
        int row = wn + np * 16 + b_row;
        b_base[np] = row * 128;
        b_xm[np] = row & 7;
    }

    int cs = 0, ls = GSTAGES - 1;
    for (int it = 0; it < GNITER; it++) {
        CP_WAIT1();
        __syncthreads();
        const uint32_t sA = sAb + cs * TILE_B;
        const uint32_t sB = sBb + cs * TILE_B;

#pragma unroll
        for (int ks = 0; ks < 4; ks++) {
            uint32_t af[4][4];
#pragma unroll
            for (int mt = 0; mt < 4; mt++)
                ldmx4(af[mt][0], af[mt][1], af[mt][2], af[mt][3],
                      sA + a_base[mt] + (((ks * 2 + a_kh) ^ a_xm[mt]) << 4));
            uint32_t bfr[2][4];
#pragma unroll
            for (int np = 0; np < 2; np++)
                ldmx4(bfr[np][0], bfr[np][1], bfr[np][2], bfr[np][3],
                      sB + b_base[np] + (((ks * 2 + b_kh) ^ b_xm[np]) << 4));
#pragma unroll
            for (int mt = 0; mt < 4; mt++)
#pragma unroll
                for (int nt = 0; nt < 4; nt++)
                    mma_bf16(acc[mt][nt], af[mt],
                             bfr[nt >> 1][(nt & 1) * 2], bfr[nt >> 1][(nt & 1) * 2 + 1]);
        }

        const int li = it + GSTAGES - 1;
        if (li < GNITER)
            g_load_stage(sAb + ls * TILE_B, sBb + ls * TILE_B, A, B, bm, bn, li * GBK, tid);
        CP_COMMIT();
        cs = (cs + 1 == GSTAGES) ? 0 : cs + 1;
        ls = (ls + 1 == GSTAGES) ? 0 : ls + 1;
    }

    const int tq = lane >> 2, tr4 = lane & 3;
#pragma unroll
    for (int mt = 0; mt < 4; mt++) {
#pragma unroll
        for (int nt = 0; nt < 4; nt++) {
            const int row = bm + wm + mt * 16 + tq;
            const int col = bn + wn + nt * 8 + tr4 * 2;
            const float b0 = bias[col], b1 = bias[col + 1];
            float2 v0 = {acc[mt][nt][0] + b0, acc[mt][nt][1] + b1};
            float2 v1 = {acc[mt][nt][2] + b0, acc[mt][nt][3] + b1};
            *(float2*)&C[(size_t)row * Nn + col]       = v0;
            *(float2*)&C[(size_t)(row + 8) * Nn + col] = v1;
        }
    }
}

// ---------------- fused RMSNorm+RoPE+split, single global read (smem cache) -
__global__ __launch_bounds__(256)
void rms2_rope_split_kernel(const float* __restrict__ qkv,
                            const float* __restrict__ wq, const float* __restrict__ wk,
                            const float* __restrict__ cosb, const float* __restrict__ sinb,
                            __nv_bfloat16* __restrict__ qs, __nv_bfloat16* __restrict__ ks,
                            float qscale)
{
    __shared__ float rowq[DIM], rowk[DIM];
    const int row = blockIdx.x;
    const float* pq = qkv + (size_t)row * (3 * DIM);
    const float* pk = pq + DIM;
    const int tid = threadIdx.x;

    float ssq = 0.f, ssk = 0.f;
#pragma unroll
    for (int u = 0; u < 2; u++) {
        int i = (tid + u * 256) * 4;
        float4 a = *(const float4*)&pq[i];
        float4 b = *(const float4*)&pk[i];
        ssq += a.x * a.x + a.y * a.y + a.z * a.z + a.w * a.w;
        ssk += b.x * b.x + b.y * b.y + b.z * b.z + b.w * b.w;
        *(float4*)&rowq[i] = a;
        *(float4*)&rowk[i] = b;
    }
#pragma unroll
    for (int off = 16; off > 0; off >>= 1) {
        ssq += __shfl_xor_sync(0xffffffffu, ssq, off);
        ssk += __shfl_xor_sync(0xffffffffu, ssk, off);
    }
    __shared__ float redq[8], redk[8];
    __shared__ float scq_s, sck_s;
    if ((tid & 31) == 0) { redq[tid >> 5] = ssq; redk[tid >> 5] = ssk; }
    __syncthreads();
    if (tid == 0) {
        float tq = 0.f, tk = 0.f;
#pragma unroll
        for (int i = 0; i < 8; i++) { tq += redq[i]; tk += redk[i]; }
        scq_s = rsqrtf(tq / (float)DIM + 1e-6f);
        sck_s = rsqrtf(tk / (float)DIM + 1e-6f);
    }
    __syncthreads();
    const float scq = scq_s, sck = sck_s;

    const float* crow = cosb + (size_t)row * HD;
    const float* srow = sinb + (size_t)row * HD;
#pragma unroll
    for (int u = 0; u < 4; u++) {
        int pi = tid + u * 256;
        int i0 = 2 * pi;
        int h = i0 >> 7;
        int d = i0 & (HD - 1);
        float c = crow[d], s = srow[d];
        const size_t hsoff = (size_t)h * S_LEN * 256 + (size_t)row * 256;
        {
            float e = rowq[i0]     * scq * wq[i0];
            float o = rowq[i0 + 1] * scq * wq[i0 + 1];
            float rx = (e * c - o * s) * qscale;
            float ry = (o * c + e * s) * qscale;
            uint32_t hi, lo;
            split2(rx, ry, hi, lo);
            __nv_bfloat16* base = qs + hsoff;
            *(uint32_t*)&base[d]       = hi;
            *(uint32_t*)&base[128 + d] = lo;
        }
        {
            float e = rowk[i0]     * sck * wk[i0];
            float o = rowk[i0 + 1] * sck * wk[i0 + 1];
            float rx = e * c - o * s;
            float ry = o * c + e * s;
            uint32_t hi, lo;
            split2(rx, ry, hi, lo);
            __nv_bfloat16* base = ks + hsoff;
            *(uint32_t*)&base[d]       = hi;
            *(uint32_t*)&base[128 + d] = lo;
        }
    }
}

// ---------------- V transpose + split -> [NH][256][S], 4B stores ------------
__global__ __launch_bounds__(256)
void vsplit_t_kernel(const float* __restrict__ qkv, __nv_bfloat16* __restrict__ vt)
{
    __shared__ float tile[32][33];
    const int s0 = blockIdx.x * 32;
    const int c0 = blockIdx.y * 32;
    const int tx = threadIdx.x & 31;
    const int ty = threadIdx.x >> 5;

#pragma unroll
    for (int i = 0; i < 4; i++) {
        int r = ty + i * 8;
        tile[r][tx] = qkv[(size_t)(s0 + r) * (3 * DIM) + 2 * DIM + c0 + tx];
    }
    __syncthreads();
    const int sx = (threadIdx.x & 15) * 2;
    const int dr0 = threadIdx.x >> 4;
#pragma unroll
    for (int i = 0; i < 2; i++) {
        int dr = dr0 + i * 16;
        int dg = c0 + dr;
        int h = dg >> 7, d = dg & 127;
        float v0 = tile[sx][dr];
        float v1 = tile[sx + 1][dr];
        uint32_t hi, lo;
        split2(v0, v1, hi, lo);
        size_t base = (size_t)h * 256 * S_LEN;
        *(uint32_t*)&vt[base + (size_t)d * S_LEN + s0 + sx]         = hi;
        *(uint32_t*)&vt[base + (size_t)(d + 128) * S_LEN + s0 + sx] = lo;
    }
}

// ---------------- tensor-core flash attention, ILP-scheduled inner loops ----
#define K_SM_BYTES  (64 * 512)
#define V_SM_BYTES  (256 * 128)
#define KV_ST       (K_SM_BYTES + V_SM_BYTES)
#define ATTN_SMEM   (3 * KV_ST)

__device__ __forceinline__ void attn_load_kv(uint32_t kvb,
    const __nv_bfloat16* __restrict__ ksrc0, const __nv_bfloat16* __restrict__ vsrc0,
    int kt, int tid)
{
    const __nv_bfloat16* ksrc = ksrc0 + (size_t)kt * 64 * 256;
#pragma unroll
    for (int u = 0; u < 8; u++) {
        int c = tid + u * 256;
        int r = c >> 5, ch = c & 31;
        cp_async16(kvb + r * 512 + ((ch ^ (r & 7)) << 4), ksrc + (size_t)r * 256 + ch * 8);
    }
    const __nv_bfloat16* vsrc = vsrc0 + kt * 64;
    const uint32_t vb = kvb + K_SM_BYTES;
#pragma unroll
    for (int u = 0; u < 8; u++) {
        int c = tid + u * 256;
        int r = c >> 3, ch = c & 7;
        cp_async16(vb + r * 128 + ((ch ^ (r & 7)) << 4), vsrc + (size_t)r * S_LEN + ch * 8);
    }
}

__global__ __launch_bounds__(256, 1)
void attn_mma_kernel(const __nv_bfloat16* __restrict__ qs,
                     const __nv_bfloat16* __restrict__ ks,
                     const __nv_bfloat16* __restrict__ vt,
                     __nv_bfloat16* __restrict__ ao3, const int* __restrict__ seq_lens)
{
    extern __shared__ __align__(1024) char smem[];
    const uint32_t sb = smem_u32(smem);
    const int tid = threadIdx.x, lane = tid & 31, wid = tid >> 5;
    const int qb = blockIdx.x, h = blockIdx.y;

    const int seqlen = seq_lens[0];
    const int ntiles = (seqlen + 63) >> 6;

    const __nv_bfloat16* qsrc  = qs + ((size_t)h * S_LEN + qb * 128) * 256;
    const __nv_bfloat16* ksrc0 = ks + (size_t)h * S_LEN * 256;
    const __nv_bfloat16* vsrc0 = vt + (size_t)h * 256 * S_LEN;

    const uint32_t qtmp = sb + 2 * KV_ST;
#pragma unroll
    for (int u = 0; u < 16; u++) {
        int c = tid + u * 256;
        int r = c >> 5, ch = c & 31;
        cp_async16(qtmp + r * 512 + ((ch ^ (r & 7)) << 4), qsrc + (size_t)r * 256 + ch * 8);
    }
    CP_COMMIT();
    attn_load_kv(sb, ksrc0, vsrc0, 0, tid);
    CP_COMMIT();
    CP_WAIT1();
    __syncthreads();

    const int a_row = wid * 16 + (lane & 15);
    const uint32_t a_off = a_row * 512;
    const int a_x = a_row & 7;
    const int a_k16 = lane >> 4;
    uint32_t qh[8][4], ql[8][4];
#pragma unroll
    for (int kst = 0; kst < 8; kst++) {
        ldmx4(qh[kst][0], qh[kst][1], qh[kst][2], qh[kst][3],
              qtmp + a_off + (((kst * 2 + a_k16) ^ a_x) << 4));
        ldmx4(ql[kst][0], ql[kst][1], ql[kst][2], ql[kst][3],
              qtmp + a_off + (((16 + kst * 2 + a_k16) ^ a_x) << 4));
    }
    __syncthreads();

    if (ntiles > 1) {
        attn_load_kv(sb + KV_ST, ksrc0, vsrc0, 1, tid);
        CP_COMMIT();
    }

    const int b_row = (lane & 7) + ((lane >> 4) << 3);
    const int b_k16 = (lane >> 3) & 1;

    uint32_t kb_off[4]; int kb_x[4];
#pragma unroll
    for (int np = 0; np < 4; np++) {
        int row = np * 16 + b_row;
        kb_off[np] = row * 512; kb_x[np] = row & 7;
    }
    uint32_t vb_off[8]; int vb_x[8];
#pragma unroll
    for (int np = 0; np < 8; np++) {
        int row = np * 16 + b_row;
        vb_off[np] = row * 128; vb_x[np] = row & 7;
    }

    float o[16][4];
#pragma unroll
    for (int nt = 0; nt < 16; nt++)
#pragma unroll
        for (int c = 0; c < 4; c++) o[nt][c] = 0.f;
    float mA = -1e30f, mB = -1e30f, lA = 0.f, lB = 0.f;

    int stg = 0;
    for (int kt = 0; kt < ntiles; kt++) {
        if (kt + 2 < ntiles) {
            int ps = stg + 2; if (ps >= 3) ps -= 3;
            attn_load_kv(sb + ps * KV_ST, ksrc0, vsrc0, kt + 2, tid);
            CP_COMMIT();
        }
        const int na = ntiles - 1 - kt;
        if (na >= 2)      { CP_WAIT2(); }
        else if (na == 1) { CP_WAIT1(); }
        else              { CP_WAIT0(); }
        __syncthreads();
        const uint32_t ksm = sb + stg * KV_ST;
        const uint32_t vsm = ksm + K_SM_BYTES;

        float s[8][4];
#pragma unroll
        for (int nt = 0; nt < 8; nt++)
#pragma unroll
            for (int c = 0; c < 4; c++) s[nt][c] = 0.f;

        // ---- QK^T: load all K frags per kst, then term-major MMAs ----
#pragma unroll
        for (int kst = 0; kst < 8; kst++) {
            uint32_t bh[4][4], bl[4][4];
#pragma unroll
            for (int np = 0; np < 4; np++) {
                ldmx4(bh[np][0], bh[np][1], bh[np][2], bh[np][3],
                      ksm + kb_off[np] + (((kst * 2 + b_k16) ^ kb_x[np]) << 4));
                ldmx4(bl[np][0], bl[np][1], bl[np][2], bl[np][3],
                      ksm + kb_off[np] + (((16 + kst * 2 + b_k16) ^ kb_x[np]) << 4));
            }
#pragma unroll
            for (int np = 0; np < 4; np++) {
                mma_bf16(s[2*np],   qh[kst], bh[np][0], bh[np][1]);
                mma_bf16(s[2*np+1], qh[kst], bh[np][2], bh[np][3]);
            }
#pragma unroll
            for (int np = 0; np < 4; np++) {
                mma_bf16(s[2*np],   qh[kst], bl[np][0], bl[np][1]);
                mma_bf16(s[2*np+1], qh[kst], bl[np][2], bl[np][3]);
            }
#pragma unroll
            for (int np = 0; np < 4; np++) {
                mma_bf16(s[2*np],   ql[kst], bh[np][0], bh[np][1]);
                mma_bf16(s[2*np+1], ql[kst], bh[np][2], bh[np][3]);
            }
        }

        if (kt * 64 + 64 > seqlen) {
            const int kbase = kt * 64 + (lane & 3) * 2;
#pragma unroll
            for (int nt = 0; nt < 8; nt++)
#pragma unroll
                for (int c = 0; c < 4; c++) {
                    int gk = kbase + nt * 8 + (c & 1);
                    if (gk >= seqlen) s[nt][c] = -1e30f;
                }
        }

        float pmA = -1e30f, pmB = -1e30f;
#pragma unroll
        for (int nt = 0; nt < 8; nt++) {
            pmA = fmaxf(pmA, fmaxf(s[nt][0], s[nt][1]));
            pmB = fmaxf(pmB, fmaxf(s[nt][2], s[nt][3]));
        }
        pmA = fmaxf(pmA, __shfl_xor_sync(0xffffffffu, pmA, 1));
        pmA = fmaxf(pmA, __shfl_xor_sync(0xffffffffu, pmA, 2));
        pmB = fmaxf(pmB, __shfl_xor_sync(0xffffffffu, pmB, 1));
        pmB = fmaxf(pmB, __shfl_xor_sync(0xffffffffu, pmB, 2));

        const float mnA = fmaxf(mA, pmA), mnB = fmaxf(mB, pmB);
        const float fA = __expf(mA - mnA), fB = __expf(mB - mnB);
        float sumA = 0.f, sumB = 0.f;

        // ---- o rescale (before any PV accumulate this tile) ----
#pragma unroll
        for (int nt = 0; nt < 16; nt++) {
            o[nt][0] *= fA; o[nt][1] *= fA;
            o[nt][2] *= fB; o[nt][3] *= fB;
        }

        // ---- chunked exp/split + PV in two np-halves, term-major ----
#pragma unroll
        for (int kk = 0; kk < 4; kk++) {
            const int n0 = 2 * kk, n1 = 2 * kk + 1;
            s[n0][0] = __expf(s[n0][0] - mnA); sumA += s[n0][0];
            s[n0][1] = __expf(s[n0][1] - mnA); sumA += s[n0][1];
            s[n0][2] = __expf(s[n0][2] - mnB); sumB += s[n0][2];
            s[n0][3] = __expf(s[n0][3] - mnB); sumB += s[n0][3];
            s[n1][0] = __expf(s[n1][0] - mnA); sumA += s[n1][0];
            s[n1][1] = __expf(s[n1][1] - mnA); sumA += s[n1][1];
            s[n1][2] = __expf(s[n1][2] - mnB); sumB += s[n1][2];
            s[n1][3] = __expf(s[n1][3] - mnB); sumB += s[n1][3];

            uint32_t ph[4], pl[4];
            split2(s[n0][0], s[n0][1], ph[0], pl[0]);
            split2(s[n0][2], s[n0][3], ph[1], pl[1]);
            split2(s[n1][0], s[n1][1], ph[2], pl[2]);
            split2(s[n1][2], s[n1][3], ph[3], pl[3]);

#pragma unroll
            for (int hnp = 0; hnp < 2; hnp++) {
                uint32_t bvh[4][4], bvl[4][4];
#pragma unroll
                for (int j = 0; j < 4; j++) {
                    const int np = hnp * 4 + j;
                    ldmx4(bvh[j][0], bvh[j][1], bvh[j][2], bvh[j][3],
                          vsm + vb_off[np] + (((kk * 2 + b_k16) ^ vb_x[np]) << 4));
                    ldmx4(bvl[j][0], bvl[j][1], bvl[j][2], bvl[j][3],
                          vsm + 128 * 128 + vb_off[np] + (((kk * 2 + b_k16) ^ vb_x[np]) << 4));
                }
#pragma unroll
                for (int j = 0; j < 4; j++) {
                    const int np = hnp * 4 + j;
                    mma_bf16(o[2*np],   ph, bvh[j][0], bvh[j][1]);
                    mma_bf16(o[2*np+1], ph, bvh[j][2], bvh[j][3]);
                }
#pragma unroll
                for (int j = 0; j < 4; j++) {
                    const int np = hnp * 4 + j;
                    mma_bf16(o[2*np],   ph, bvl[j][0], bvl[j][1]);
                    mma_bf16(o[2*np+1], ph, bvl[j][2], bvl[j][3]);
                }
#pragma unroll
                for (int j = 0; j < 4; j++) {
                    const int np = hnp * 4 + j;
                    mma_bf16(o[2*np],   pl, bvh[j][0], bvh[j][1]);
                    mma_bf16(o[2*np+1], pl, bvh[j][2], bvh[j][3]);
                }
            }
        }

        sumA += __shfl_xor_sync(0xffffffffu, sumA, 1);
        sumA += __shfl_xor_sync(0xffffffffu, sumA, 2);
        sumB += __shfl_xor_sync(0xffffffffu, sumB, 1);
        sumB += __shfl_xor_sync(0xffffffffu, sumB, 2);
        mA = mnA; mB = mnB;
        lA = lA * fA + sumA;
        lB = lB * fB + sumB;

        __syncthreads();
        stg = (stg + 1 == 3) ? 0 : stg + 1;
    }

    const float iA = 1.f / lA, iB = 1.f / lB;
    const int row0 = qb * 128 + wid * 16 + (lane >> 2);
    const int col0 = h * 128 + (lane & 3) * 2;
#pragma unroll
    for (int nt = 0; nt < 16; nt++) {
        float xA = o[nt][0] * iA, yA = o[nt][1] * iA;
        float xB = o[nt][2] * iB, yB = o[nt][3] * iB;
        uint32_t hA, loA, hB, loB;
        split2(xA, yA, hA, loA);
        split2(xB, yB, hB, loB);
        __nv_bfloat16* pA = ao3 + (size_t)row0 * K3 + col0 + nt * 8;
        __nv_bfloat16* pB = ao3 + (size_t)(row0 + 8) * K3 + col0 + nt * 8;
        *(uint32_t*)&pA[0]        = hA;
        *(uint32_t*)&pA[DIM]      = hA;
        *(uint32_t*)&pA[2 * DIM]  = loA;
        *(uint32_t*)&pB[0]        = hB;
        *(uint32_t*)&pB[DIM]      = hB;
        *(uint32_t*)&pB[2 * DIM]  = loB;
    }
}

// ---------------- launch ----------------------------------------------------
extern "C" void kernel_launch(void* const* d_in, const int* in_sizes, int n_in,
                              void* d_out, int out_size)
{
    const float* x    = (const float*)d_in[0];
    const float* Wq   = (const float*)d_in[1];
    const float* bq   = (const float*)d_in[2];
    const float* Wk   = (const float*)d_in[3];
    const float* bk   = (const float*)d_in[4];
    const float* Wv   = (const float*)d_in[5];
    const float* bv   = (const float*)d_in[6];
    const float* Wo   = (const float*)d_in[7];
    const float* bo   = (const float*)d_in[8];
    const float* nqw  = (const float*)d_in[9];
    const float* nkw  = (const float*)d_in[10];
    const float* cosb = (const float*)d_in[11];
    const float* sinb = (const float*)d_in[12];
    const int*   seql = (const int*)d_in[13];
    float* out = (float*)d_out;

    float *qkv, *bias3;
    __nv_bfloat16 *x3, *ao3, *w3, *qsb, *ksb, *vtb;
    cudaGetSymbolAddress((void**)&qkv,   g_qkv);
    cudaGetSymbolAddress((void**)&bias3, g_bias3);
    cudaGetSymbolAddress((void**)&x3,    g_x3);
    cudaGetSymbolAddress((void**)&ao3,   g_ao3);
    cudaGetSymbolAddress((void**)&w3,    g_w3);
    cudaGetSymbolAddress((void**)&qsb,   g_qs);
    cudaGetSymbolAddress((void**)&ksb,   g_ks);
    cudaGetSymbolAddress((void**)&vtb,   g_vt);

    cudaFuncSetAttribute(gemm_mma_kernel, cudaFuncAttributeMaxDynamicSharedMemorySize, SMEM_G);
    cudaFuncSetAttribute(attn_mma_kernel, cudaFuncAttributeMaxDynamicSharedMemorySize, ATTN_SMEM);

    cvt_all_kernel<<<CVT_BLOCKS, 256>>>(x, Wq, Wk, Wv, Wo, bq, bk, bv, x3, w3, bias3);

    gemm_mma_kernel<<<dim3(3 * DIM / GBN, S_LEN / GBM), 256, SMEM_G>>>(
        x3, w3, bias3, qkv, 3 * DIM);

    const float qscale = 0.08838834764831845f;   // 1/sqrt(128)
    rms2_rope_split_kernel<<<S_LEN, 256>>>(qkv, nqw, nkw, cosb, sinb, qsb, ksb, qscale);
    vsplit_t_kernel<<<dim3(S_LEN / 32, DIM / 32), 256>>>(qkv, vtb);

    attn_mma_kernel<<<dim3(S_LEN / 128, NH), 256, ATTN_SMEM>>>(qsb, ksb, vtb, ao3, seql);

    gemm_mma_kernel<<<dim3(DIM / GBN, S_LEN / GBM), 256, SMEM_G>>>(
        ao3, w3 + 3 * (size_t)DIM * K3, bo, out, DIM);
}